// round 2
// baseline (speedup 1.0000x reference)
#include <cuda_runtime.h>
#include <math.h>

// ---------------------------------------------------------------------------
// Constants
// ---------------------------------------------------------------------------
#define SEQ   2048
#define HID   768
#define NQ    12
#define NKV   3
#define HD    64
#define QKVC  1152          // (NQ + 2*NKV) * HD
#define NE    16
#define FF    1536
#define SLOTS 4096          // SEQ * TOPK

// ---------------------------------------------------------------------------
// Device scratch (no allocations allowed -> __device__ globals)
// NOTE: device globals must only be referenced from DEVICE code. Passing them
// as kernel arguments from host passes the host shadow address (silently
// "works" on GB300 via ATS but reads/writes the wrong memory).
// ---------------------------------------------------------------------------
__device__ float g_xn1[SEQ * HID];
__device__ float g_qkv[SEQ * QKVC];
__device__ float g_Q[NQ * SEQ * HD];
__device__ float g_K[NKV * SEQ * HD];
__device__ float g_V[NKV * SEQ * HD];
__device__ float g_attn[SEQ * HID];
__device__ float g_h1[SEQ * HID];
__device__ float g_xn2[SEQ * HID];
__device__ int   g_eid[SLOTS];
__device__ float g_ew[SLOTS];
__device__ int   g_cnt[NE];
__device__ int   g_off[NE + 1];
__device__ int   g_cur[NE];
__device__ int   g_ptok[SLOTS];
__device__ int   g_tslot[SLOTS];
__device__ float g_Xp[(size_t)SLOTS * HID];
__device__ float g_Hgu[(size_t)SLOTS * 2 * FF];
__device__ float g_Hact[(size_t)SLOTS * FF];
__device__ float g_Dn[(size_t)SLOTS * HID];

// ---------------------------------------------------------------------------
// RMSNorm kernels (globals referenced in device code only)
// ---------------------------------------------------------------------------
__device__ __forceinline__ void rmsnorm_row(const float* __restrict__ xr,
                                            const float* __restrict__ w,
                                            float* __restrict__ yr) {
    float s = 0.f;
    for (int i = threadIdx.x; i < HID; i += 256) {
        float v = xr[i];
        s += v * v;
    }
    __shared__ float red[256];
    red[threadIdx.x] = s;
    __syncthreads();
    for (int o = 128; o > 0; o >>= 1) {
        if (threadIdx.x < o) red[threadIdx.x] += red[threadIdx.x + o];
        __syncthreads();
    }
    float scale = rsqrtf(red[0] / (float)HID + 1e-6f);
    for (int i = threadIdx.x; i < HID; i += 256)
        yr[i] = xr[i] * scale * w[i];
}

__global__ void k_rmsnorm1(const float* __restrict__ x, const float* __restrict__ w) {
    int row = blockIdx.x;
    rmsnorm_row(x + (size_t)row * HID, w, g_xn1 + (size_t)row * HID);
}

__global__ void k_rmsnorm2(const float* __restrict__ w) {
    int row = blockIdx.x;
    rmsnorm_row(g_h1 + (size_t)row * HID, w, g_xn2 + (size_t)row * HID);
}

// ---------------------------------------------------------------------------
// Generic 128x128x8 SGEMM core, 256 threads, 8x8 per thread.
// ---------------------------------------------------------------------------
__device__ __forceinline__ void gemm_core(const float* __restrict__ A, int lda,
                                          const float* __restrict__ B, int ldb,
                                          int K, int rows, float acc[8][8]) {
    __shared__ float sA[8][128];
    __shared__ float sB[8][128];
    int tid  = threadIdx.x;
    int tx   = tid & 15;
    int ty   = tid >> 4;
    int arow = tid >> 1;
    int akq  = (tid & 1) * 4;
    int bkr  = tid >> 5;
    int bcol = (tid & 31) * 4;

    for (int k0 = 0; k0 < K; k0 += 8) {
        float4 av = make_float4(0.f, 0.f, 0.f, 0.f);
        if (arow < rows)
            av = *reinterpret_cast<const float4*>(A + (size_t)arow * lda + k0 + akq);
        float4 bv = *reinterpret_cast<const float4*>(B + (size_t)(k0 + bkr) * ldb + bcol);
        __syncthreads();
        sA[akq + 0][arow] = av.x;
        sA[akq + 1][arow] = av.y;
        sA[akq + 2][arow] = av.z;
        sA[akq + 3][arow] = av.w;
        *reinterpret_cast<float4*>(&sB[bkr][bcol]) = bv;
        __syncthreads();
#pragma unroll
        for (int kk = 0; kk < 8; kk++) {
            float4 a0 = *reinterpret_cast<const float4*>(&sA[kk][ty * 8]);
            float4 a1 = *reinterpret_cast<const float4*>(&sA[kk][ty * 8 + 4]);
            float4 b0 = *reinterpret_cast<const float4*>(&sB[kk][tx * 8]);
            float4 b1 = *reinterpret_cast<const float4*>(&sB[kk][tx * 8 + 4]);
            float ar[8] = {a0.x, a0.y, a0.z, a0.w, a1.x, a1.y, a1.z, a1.w};
            float br[8] = {b0.x, b0.y, b0.z, b0.w, b1.x, b1.y, b1.z, b1.w};
#pragma unroll
            for (int r = 0; r < 8; r++)
#pragma unroll
                for (int c = 0; c < 8; c++) acc[r][c] += ar[r] * br[c];
        }
    }
}

// QKV projection: g_qkv = g_xn1 @ w_qkv   (2048 x 768 x 1152)
__global__ void k_gemm_qkv(const float* __restrict__ W) {
    int mb = blockIdx.x, nb = blockIdx.y;
    float acc[8][8] = {};
    gemm_core(g_xn1 + (size_t)mb * 128 * HID, HID, W + nb * 128, QKVC, HID, 128, acc);
    int tx = threadIdx.x & 15, ty = threadIdx.x >> 4;
    float* Cp = g_qkv + (size_t)(mb * 128) * QKVC + nb * 128;
#pragma unroll
    for (int r = 0; r < 8; r++) {
        float* crow = Cp + (size_t)(ty * 8 + r) * QKVC + tx * 8;
        *reinterpret_cast<float4*>(crow)     = make_float4(acc[r][0], acc[r][1], acc[r][2], acc[r][3]);
        *reinterpret_cast<float4*>(crow + 4) = make_float4(acc[r][4], acc[r][5], acc[r][6], acc[r][7]);
    }
}

// Out projection + residual: g_h1 = x + g_attn @ w_out   (2048 x 768 x 768)
__global__ void k_gemm_out(const float* __restrict__ W, const float* __restrict__ xres) {
    int mb = blockIdx.x, nb = blockIdx.y;
    float acc[8][8] = {};
    gemm_core(g_attn + (size_t)mb * 128 * HID, HID, W + nb * 128, HID, HID, 128, acc);
    int tx = threadIdx.x & 15, ty = threadIdx.x >> 4;
    size_t base = (size_t)(mb * 128) * HID + nb * 128;
#pragma unroll
    for (int r = 0; r < 8; r++) {
        size_t off = base + (size_t)(ty * 8 + r) * HID + tx * 8;
        float4 r0 = *reinterpret_cast<const float4*>(xres + off);
        float4 r1 = *reinterpret_cast<const float4*>(xres + off + 4);
        float4 o0 = make_float4(r0.x + acc[r][0], r0.y + acc[r][1], r0.z + acc[r][2], r0.w + acc[r][3]);
        float4 o1 = make_float4(r1.x + acc[r][4], r1.y + acc[r][5], r1.z + acc[r][6], r1.w + acc[r][7]);
        *reinterpret_cast<float4*>(g_h1 + off)     = o0;
        *reinterpret_cast<float4*>(g_h1 + off + 4) = o1;
    }
}

// MoE GEMM1: Hgu[slot] = Xp[slot] @ w_gate_up[e]   (rows_e x 768 x 3072)
__global__ void k_moe_gemm1(const float* __restrict__ Wgu) {
    int e = blockIdx.x >> 5, mb = blockIdx.x & 31, nb = blockIdx.y;
    int r0 = g_off[e];
    int rows_e = g_off[e + 1] - r0;
    int rbase = mb * 128;
    if (rbase >= rows_e) return;
    int rows = min(128, rows_e - rbase);
    float acc[8][8] = {};
    gemm_core(g_Xp + (size_t)(r0 + rbase) * HID, HID,
              Wgu + (size_t)e * HID * (2 * FF) + nb * 128, 2 * FF, HID, rows, acc);
    int tx = threadIdx.x & 15, ty = threadIdx.x >> 4;
    float* Cp = g_Hgu + (size_t)(r0 + rbase) * (2 * FF) + nb * 128;
#pragma unroll
    for (int r = 0; r < 8; r++) {
        int row = ty * 8 + r;
        if (row >= rows) break;
        float* crow = Cp + (size_t)row * (2 * FF) + tx * 8;
        *reinterpret_cast<float4*>(crow)     = make_float4(acc[r][0], acc[r][1], acc[r][2], acc[r][3]);
        *reinterpret_cast<float4*>(crow + 4) = make_float4(acc[r][4], acc[r][5], acc[r][6], acc[r][7]);
    }
}

// MoE GEMM2: Dn[slot] = Hact[slot] @ w_down[e]   (rows_e x 1536 x 768)
__global__ void k_moe_gemm2(const float* __restrict__ Wd) {
    int e = blockIdx.x >> 5, mb = blockIdx.x & 31, nb = blockIdx.y;
    int r0 = g_off[e];
    int rows_e = g_off[e + 1] - r0;
    int rbase = mb * 128;
    if (rbase >= rows_e) return;
    int rows = min(128, rows_e - rbase);
    float acc[8][8] = {};
    gemm_core(g_Hact + (size_t)(r0 + rbase) * FF, FF,
              Wd + (size_t)e * FF * HID + nb * 128, HID, FF, rows, acc);
    int tx = threadIdx.x & 15, ty = threadIdx.x >> 4;
    float* Cp = g_Dn + (size_t)(r0 + rbase) * HID + nb * 128;
#pragma unroll
    for (int r = 0; r < 8; r++) {
        int row = ty * 8 + r;
        if (row >= rows) break;
        float* crow = Cp + (size_t)row * HID + tx * 8;
        *reinterpret_cast<float4*>(crow)     = make_float4(acc[r][0], acc[r][1], acc[r][2], acc[r][3]);
        *reinterpret_cast<float4*>(crow + 4) = make_float4(acc[r][4], acc[r][5], acc[r][6], acc[r][7]);
    }
}

// ---------------------------------------------------------------------------
// RoPE + split qkv into head-major Q/K/V. One block per seq position, 576 thr.
// ---------------------------------------------------------------------------
__global__ void k_rope(void) {
    int s = blockIdx.x;
    int p = threadIdx.x;
    const float* row = g_qkv + (size_t)s * QKVC;
    if (p < 384) {                       // Q: 12 heads * 32 pairs
        int h = p >> 5, i = p & 31;
        float v0 = row[h * HD + 2 * i];
        float v1 = row[h * HD + 2 * i + 1];
        float inv = powf(10000.f, -(float)(2 * i) / (float)HD);
        float ang = (float)s * inv;
        float sn, cs;
        sincosf(ang, &sn, &cs);
        float* dst = g_Q + ((size_t)h * SEQ + s) * HD;
        dst[2 * i]     = v0 * cs - v1 * sn;
        dst[2 * i + 1] = v0 * sn + v1 * cs;
    } else if (p < 480) {                // K: 3 heads * 32 pairs
        int q = p - 384;
        int h = q >> 5, i = q & 31;
        float v0 = row[NQ * HD + h * HD + 2 * i];
        float v1 = row[NQ * HD + h * HD + 2 * i + 1];
        float inv = powf(10000.f, -(float)(2 * i) / (float)HD);
        float ang = (float)s * inv;
        float sn, cs;
        sincosf(ang, &sn, &cs);
        float* dst = g_K + ((size_t)h * SEQ + s) * HD;
        dst[2 * i]     = v0 * cs - v1 * sn;
        dst[2 * i + 1] = v0 * sn + v1 * cs;
    } else {                             // V: copy
        int q = p - 480;
        int h = q >> 5, i = q & 31;
        float* dst = g_V + ((size_t)h * SEQ + s) * HD;
        dst[2 * i]     = row[(NQ + NKV) * HD + h * HD + 2 * i];
        dst[2 * i + 1] = row[(NQ + NKV) * HD + h * HD + 2 * i + 1];
    }
}

// ---------------------------------------------------------------------------
// Flash attention, fp32. Block = (64-query tile, head). 256 threads, 4x4/thr.
// ---------------------------------------------------------------------------
#define ATT_SMEM_FLOATS (64 * 68 * 3 + 64 * 64 + 64 * 65 + 64 * 3)

__global__ void k_attn(void) {
    extern __shared__ float sm[];
    float* Qt   = sm;                 // [64 d][68]
    float* Kt   = Qt + 64 * 68;       // [64 d][68]
    float* Pt   = Kt + 64 * 68;       // [64 j][68]
    float* Vs   = Pt + 64 * 68;       // [64 j][64]
    float* Sm   = Vs + 64 * 64;       // [64 i][65]
    float* mrow = Sm + 64 * 65;
    float* lrow = mrow + 64;
    float* arow = lrow + 64;

    int qb = blockIdx.x, h = blockIdx.y;
    int kvh = h >> 2;                 // REP = 4
    int tid = threadIdx.x, tx = tid & 15, ty = tid >> 4;

    const float* Qb = g_Q + ((size_t)h * SEQ + qb * 64) * HD;
    for (int e = tid; e < 4096; e += 256) {
        int r = e >> 6, d = e & 63;
        Qt[d * 68 + r] = Qb[r * HD + d] * 0.125f;   // 1/sqrt(64)
    }
    if (tid < 64) { mrow[tid] = -1e30f; lrow[tid] = 0.f; }

    float acc[4][4] = {};
    for (int kb = 0; kb <= qb; kb++) {
        const float* Kb = g_K + ((size_t)kvh * SEQ + kb * 64) * HD;
        const float* Vb = g_V + ((size_t)kvh * SEQ + kb * 64) * HD;
        __syncthreads();
        for (int e = tid; e < 4096; e += 256) {
            int r = e >> 6, d = e & 63;
            Kt[d * 68 + r] = Kb[r * HD + d];
            Vs[e] = Vb[e];
        }
        __syncthreads();

        float s[4][4] = {};
#pragma unroll 8
        for (int d = 0; d < 64; d++) {
            float4 qa = *reinterpret_cast<const float4*>(&Qt[d * 68 + ty * 4]);
            float4 ka = *reinterpret_cast<const float4*>(&Kt[d * 68 + tx * 4]);
            float qr[4] = {qa.x, qa.y, qa.z, qa.w};
            float kr[4] = {ka.x, ka.y, ka.z, ka.w};
#pragma unroll
            for (int r = 0; r < 4; r++)
#pragma unroll
                for (int c = 0; c < 4; c++) s[r][c] += qr[r] * kr[c];
        }
        int grb = qb * 64 + ty * 4, gcb = kb * 64 + tx * 4;
#pragma unroll
        for (int r = 0; r < 4; r++)
#pragma unroll
            for (int c = 0; c < 4; c++)
                Sm[(ty * 4 + r) * 65 + tx * 4 + c] =
                    (gcb + c <= grb + r) ? s[r][c] : -1e30f;
        __syncthreads();

        if (tid < 64) {
            int i = tid;
            float mx = mrow[i];
            for (int j = 0; j < 64; j++) mx = fmaxf(mx, Sm[i * 65 + j]);
            float al = __expf(mrow[i] - mx);
            float sum = 0.f;
            for (int j = 0; j < 64; j++) {
                float p = __expf(Sm[i * 65 + j] - mx);
                Pt[j * 68 + i] = p;
                sum += p;
            }
            lrow[i] = lrow[i] * al + sum;
            mrow[i] = mx;
            arow[i] = al;
        }
        __syncthreads();

#pragma unroll
        for (int r = 0; r < 4; r++) {
            float al = arow[ty * 4 + r];
#pragma unroll
            for (int c = 0; c < 4; c++) acc[r][c] *= al;
        }
#pragma unroll 8
        for (int j = 0; j < 64; j++) {
            float4 pa = *reinterpret_cast<const float4*>(&Pt[j * 68 + ty * 4]);
            float4 va = *reinterpret_cast<const float4*>(&Vs[j * 64 + tx * 4]);
            float pr[4] = {pa.x, pa.y, pa.z, pa.w};
            float vr[4] = {va.x, va.y, va.z, va.w};
#pragma unroll
            for (int r = 0; r < 4; r++)
#pragma unroll
                for (int c = 0; c < 4; c++) acc[r][c] += pr[r] * vr[c];
        }
    }

#pragma unroll
    for (int r = 0; r < 4; r++) {
        float inv = 1.f / lrow[ty * 4 + r];
        int grow = qb * 64 + ty * 4 + r;
        float4 o = make_float4(acc[r][0] * inv, acc[r][1] * inv,
                               acc[r][2] * inv, acc[r][3] * inv);
        *reinterpret_cast<float4*>(g_attn + (size_t)grow * HID + h * HD + tx * 4) = o;
    }
}

// ---------------------------------------------------------------------------
// MoE routing / permutation
// ---------------------------------------------------------------------------
__global__ void k_reset(void) {
    if (threadIdx.x < NE) {
        g_cnt[threadIdx.x] = 0;
        g_cur[threadIdx.x] = 0;
    }
}

__global__ void k_router(const float* __restrict__ Wr) {
    int t = blockIdx.x;
    int w = threadIdx.x >> 5, lane = threadIdx.x & 31;
    __shared__ float lg[NE];
    const float* xr = g_xn2 + (size_t)t * HID;
    float s = 0.f;
    for (int k = lane; k < HID; k += 32) s += xr[k] * Wr[k * NE + w];
#pragma unroll
    for (int o = 16; o > 0; o >>= 1) s += __shfl_xor_sync(0xffffffffu, s, o);
    if (lane == 0) lg[w] = s;
    __syncthreads();
    if (threadIdx.x == 0) {
        int b0 = 0;
        float v0 = lg[0];
        for (int e = 1; e < NE; e++)
            if (lg[e] > v0) { v0 = lg[e]; b0 = e; }
        int b1 = -1;
        float v1 = -3e38f;
        for (int e = 0; e < NE; e++)
            if (e != b0 && lg[e] > v1) { v1 = lg[e]; b1 = e; }
        float w0 = 1.f / (1.f + __expf(v1 - v0));
        g_eid[2 * t] = b0;
        g_eid[2 * t + 1] = b1;
        g_ew[2 * t] = w0;
        g_ew[2 * t + 1] = 1.f - w0;
        atomicAdd(&g_cnt[b0], 1);
        atomicAdd(&g_cnt[b1], 1);
    }
}

__global__ void k_scan(void) {
    if (threadIdx.x == 0) {
        int a = 0;
        for (int e = 0; e < NE; e++) {
            g_off[e] = a;
            a += g_cnt[e];
        }
        g_off[NE] = a;
    }
}

__global__ void k_scatter(void) {
    int t = blockIdx.x * blockDim.x + threadIdx.x;
    if (t >= SEQ) return;
#pragma unroll
    for (int slot = 0; slot < 2; slot++) {
        int e = g_eid[2 * t + slot];
        int pos = g_off[e] + atomicAdd(&g_cur[e], 1);
        g_ptok[pos] = t;
        g_tslot[2 * t + slot] = pos;
    }
}

__global__ void k_gather(void) {
    int pos = blockIdx.x;
    int tok = g_ptok[pos];
    const float4* src = reinterpret_cast<const float4*>(g_xn2 + (size_t)tok * HID);
    float4* dst = reinterpret_cast<float4*>(g_Xp + (size_t)pos * HID);
    dst[threadIdx.x] = src[threadIdx.x];   // 192 threads * float4 = 768
}

__global__ void k_silu(void) {
    int idx = blockIdx.x * blockDim.x + threadIdx.x;
    const int total = SLOTS * FF;
    if (idx >= total) return;
    int pos = idx / FF, j = idx - pos * FF;
    float g = g_Hgu[(size_t)pos * (2 * FF) + j];
    float u = g_Hgu[(size_t)pos * (2 * FF) + FF + j];
    float sg = g / (1.f + __expf(-g));
    g_Hact[idx] = sg * u;
}

__global__ void k_combine(float* __restrict__ out) {
    int t = blockIdx.x;
    int i = threadIdx.x;                  // 192 float4
    int p0 = g_tslot[2 * t], p1 = g_tslot[2 * t + 1];
    float w0 = g_ew[2 * t], w1 = g_ew[2 * t + 1];
    float4 a = reinterpret_cast<const float4*>(g_h1 + (size_t)t * HID)[i];
    float4 b = reinterpret_cast<const float4*>(g_Dn + (size_t)p0 * HID)[i];
    float4 c = reinterpret_cast<const float4*>(g_Dn + (size_t)p1 * HID)[i];
    float4 o = make_float4(a.x + w0 * b.x + w1 * c.x,
                           a.y + w0 * b.y + w1 * c.y,
                           a.z + w0 * b.z + w1 * c.z,
                           a.w + w0 * b.w + w1 * c.w);
    reinterpret_cast<float4*>(out + (size_t)t * HID)[i] = o;
}

// ---------------------------------------------------------------------------
// Launch
// ---------------------------------------------------------------------------
extern "C" void kernel_launch(void* const* d_in, const int* in_sizes, int n_in,
                              void* d_out, int out_size) {
    (void)in_sizes; (void)n_in; (void)out_size;
    const float* x        = (const float*)d_in[0];
    const float* norm1_w  = (const float*)d_in[1];
    const float* w_qkv    = (const float*)d_in[2];
    const float* w_out    = (const float*)d_in[3];
    const float* norm2_w  = (const float*)d_in[4];
    const float* w_router = (const float*)d_in[5];
    const float* w_gateup = (const float*)d_in[6];
    const float* w_down   = (const float*)d_in[7];
    float* out = (float*)d_out;

    const int att_smem = ATT_SMEM_FLOATS * (int)sizeof(float);
    cudaFuncSetAttribute(k_attn, cudaFuncAttributeMaxDynamicSharedMemorySize, att_smem);

    k_reset<<<1, 32>>>();
    k_rmsnorm1<<<SEQ, 256>>>(x, norm1_w);
    k_gemm_qkv<<<dim3(SEQ / 128, QKVC / 128), 256>>>(w_qkv);
    k_rope<<<SEQ, 576>>>();
    k_attn<<<dim3(SEQ / 64, NQ), 256, att_smem>>>();
    k_gemm_out<<<dim3(SEQ / 128, HID / 128), 256>>>(w_out, x);
    k_rmsnorm2<<<SEQ, 256>>>(norm2_w);
    k_router<<<SEQ, 512>>>(w_router);
    k_scan<<<1, 32>>>();
    k_scatter<<<(SEQ + 255) / 256, 256>>>();
    k_gather<<<SLOTS, 192>>>();
    k_moe_gemm1<<<dim3(NE * 32, (2 * FF) / 128), 256>>>(w_gateup);
    k_silu<<<(SLOTS * FF + 255) / 256, 256>>>();
    k_moe_gemm2<<<dim3(NE * 32, HID / 128), 256>>>(w_down);
    k_combine<<<SEQ, 192>>>(out);
}

// round 3
// speedup vs baseline: 1.8284x; 1.8284x over previous
#include <cuda_runtime.h>
#include <math.h>

// ---------------------------------------------------------------------------
// Constants
// ---------------------------------------------------------------------------
#define SEQ   2048
#define HID   768
#define NQ    12
#define NKV   3
#define HD    64
#define QKVC  1152          // (NQ + 2*NKV) * HD
#define NE    16
#define FF    1536
#define SLOTS 4096          // SEQ * TOPK

// ---------------------------------------------------------------------------
// Device scratch (globals only referenced from device code!)
// ---------------------------------------------------------------------------
__device__ float g_xn1[SEQ * HID];
__device__ float g_qkv[SEQ * QKVC];
__device__ float g_Q[NQ * SEQ * HD];
__device__ float g_K[NKV * SEQ * HD];
__device__ float g_V[NKV * SEQ * HD];
__device__ float g_attn[SEQ * HID];
__device__ float g_h1[SEQ * HID];
__device__ float g_xn2[SEQ * HID];
__device__ int   g_eid[SLOTS];
__device__ float g_ew[SLOTS];
__device__ int   g_cnt[NE];
__device__ int   g_off[NE + 1];
__device__ int   g_cur[NE];
__device__ int   g_ptok[SLOTS];
__device__ int   g_tslot[SLOTS];
__device__ float g_Xp[(size_t)SLOTS * HID];
__device__ float g_Hgu[(size_t)SLOTS * 2 * FF];
__device__ float g_Hact[(size_t)SLOTS * FF];
__device__ float g_Dn[(size_t)SLOTS * HID];

// ---------------------------------------------------------------------------
// RMSNorm
// ---------------------------------------------------------------------------
__device__ __forceinline__ void rmsnorm_row(const float* __restrict__ xr,
                                            const float* __restrict__ w,
                                            float* __restrict__ yr) {
    float s = 0.f;
    for (int i = threadIdx.x; i < HID; i += 256) {
        float v = xr[i];
        s += v * v;
    }
    __shared__ float red[256];
    red[threadIdx.x] = s;
    __syncthreads();
    for (int o = 128; o > 0; o >>= 1) {
        if (threadIdx.x < o) red[threadIdx.x] += red[threadIdx.x + o];
        __syncthreads();
    }
    float scale = rsqrtf(red[0] / (float)HID + 1e-6f);
    for (int i = threadIdx.x; i < HID; i += 256)
        yr[i] = xr[i] * scale * w[i];
}

__global__ void k_rmsnorm1(const float* __restrict__ x, const float* __restrict__ w) {
    int row = blockIdx.x;
    rmsnorm_row(x + (size_t)row * HID, w, g_xn1 + (size_t)row * HID);
}

__global__ void k_rmsnorm2(const float* __restrict__ w) {
    int row = blockIdx.x;
    rmsnorm_row(g_h1 + (size_t)row * HID, w, g_xn2 + (size_t)row * HID);
}

// ---------------------------------------------------------------------------
// TF32 tensor-core GEMM: 128x128 tile, 256 threads (8 warps, 2x4),
// warp tile 64x32 = 4x4 m16n8k8 fragments, K-step 16.
// ---------------------------------------------------------------------------
__device__ __forceinline__ unsigned f2tf(float f) {
    unsigned u;
    asm("cvt.rna.tf32.f32 %0, %1;" : "=r"(u) : "f"(f));
    return u;
}

__device__ __forceinline__ void mma_tf32(float d[4], const unsigned a[4],
                                         const unsigned b[2]) {
    asm volatile(
        "mma.sync.aligned.m16n8k8.row.col.f32.tf32.tf32.f32 "
        "{%0,%1,%2,%3}, {%4,%5,%6,%7}, {%8,%9}, {%0,%1,%2,%3};"
        : "+f"(d[0]), "+f"(d[1]), "+f"(d[2]), "+f"(d[3])
        : "r"(a[0]), "r"(a[1]), "r"(a[2]), "r"(a[3]),
          "r"(b[0]), "r"(b[1]));
}

// A: [rows x K] row-major (pre-offset to tile row 0, leading dim lda)
// B: [K x N]   row-major (pre-offset to tile col 0, leading dim ldb)
__device__ __forceinline__ void gemm_tf32_core(const float* __restrict__ A, int lda,
                                               const float* __restrict__ B, int ldb,
                                               int K, int rows, float acc[4][4][4]) {
    __shared__ unsigned sA[128][20];   // stride-20 pad: conflict-free frag loads
    __shared__ unsigned sB[16][132];
    int tid  = threadIdx.x;
    int warp = tid >> 5, lane = tid & 31;
    int wm = warp >> 2;                // 0..1
    int wn = warp & 3;                 // 0..3
    int g  = lane >> 2;                // 0..7
    int c  = lane & 3;                 // 0..3

    for (int k0 = 0; k0 < K; k0 += 16) {
        // stage A 128x16 (guarded, converted to tf32)
#pragma unroll
        for (int it = 0; it < 2; it++) {
            int idx = tid + it * 256;
            int row = idx >> 2;
            int kq  = (idx & 3) * 4;
            float4 v = make_float4(0.f, 0.f, 0.f, 0.f);
            if (row < rows)
                v = *reinterpret_cast<const float4*>(A + (size_t)row * lda + k0 + kq);
            sA[row][kq + 0] = f2tf(v.x);
            sA[row][kq + 1] = f2tf(v.y);
            sA[row][kq + 2] = f2tf(v.z);
            sA[row][kq + 3] = f2tf(v.w);
        }
        // stage B 16x128 (coalesced)
#pragma unroll
        for (int it = 0; it < 2; it++) {
            int idx = tid + it * 256;
            int kr  = idx >> 5;         // 0..15
            int c4  = (idx & 31) * 4;
            float4 v = *reinterpret_cast<const float4*>(B + (size_t)(k0 + kr) * ldb + c4);
            sB[kr][c4 + 0] = f2tf(v.x);
            sB[kr][c4 + 1] = f2tf(v.y);
            sB[kr][c4 + 2] = f2tf(v.z);
            sB[kr][c4 + 3] = f2tf(v.w);
        }
        __syncthreads();
#pragma unroll
        for (int kk = 0; kk < 16; kk += 8) {
            unsigned af[4][4];
#pragma unroll
            for (int mi = 0; mi < 4; mi++) {
                int m = wm * 64 + mi * 16;
                af[mi][0] = sA[m + g][kk + c];
                af[mi][1] = sA[m + g + 8][kk + c];
                af[mi][2] = sA[m + g][kk + c + 4];
                af[mi][3] = sA[m + g + 8][kk + c + 4];
            }
#pragma unroll
            for (int ni = 0; ni < 4; ni++) {
                int n = wn * 32 + ni * 8 + g;
                unsigned bf[2];
                bf[0] = sB[kk + c][n];
                bf[1] = sB[kk + c + 4][n];
#pragma unroll
                for (int mi = 0; mi < 4; mi++)
                    mma_tf32(acc[mi][ni], af[mi], bf);
            }
        }
        __syncthreads();
    }
}

// Epilogue helper: returns row/col of accumulator element pairs.
// c0,c1 -> (row g,   col 2c, 2c+1); c2,c3 -> (row g+8, same cols)

// QKV projection: g_qkv = g_xn1 @ w_qkv   (2048 x 768 x 1152)
__global__ void k_gemm_qkv(const float* __restrict__ W) {
    int mb = blockIdx.x, nb = blockIdx.y;
    float acc[4][4][4] = {};
    gemm_tf32_core(g_xn1 + (size_t)mb * 128 * HID, HID, W + nb * 128, QKVC, HID, 128, acc);
    int warp = threadIdx.x >> 5, lane = threadIdx.x & 31;
    int wm = warp >> 2, wn = warp & 3, g = lane >> 2, c = lane & 3;
#pragma unroll
    for (int mi = 0; mi < 4; mi++) {
#pragma unroll
        for (int ni = 0; ni < 4; ni++) {
            int r = mb * 128 + wm * 64 + mi * 16 + g;
            int col = nb * 128 + wn * 32 + ni * 8 + 2 * c;
            *reinterpret_cast<float2*>(g_qkv + (size_t)r * QKVC + col) =
                make_float2(acc[mi][ni][0], acc[mi][ni][1]);
            *reinterpret_cast<float2*>(g_qkv + (size_t)(r + 8) * QKVC + col) =
                make_float2(acc[mi][ni][2], acc[mi][ni][3]);
        }
    }
}

// Out projection + residual: g_h1 = x + g_attn @ w_out   (2048 x 768 x 768)
__global__ void k_gemm_out(const float* __restrict__ W, const float* __restrict__ xres) {
    int mb = blockIdx.x, nb = blockIdx.y;
    float acc[4][4][4] = {};
    gemm_tf32_core(g_attn + (size_t)mb * 128 * HID, HID, W + nb * 128, HID, HID, 128, acc);
    int warp = threadIdx.x >> 5, lane = threadIdx.x & 31;
    int wm = warp >> 2, wn = warp & 3, g = lane >> 2, c = lane & 3;
#pragma unroll
    for (int mi = 0; mi < 4; mi++) {
#pragma unroll
        for (int ni = 0; ni < 4; ni++) {
            int r = mb * 128 + wm * 64 + mi * 16 + g;
            int col = nb * 128 + wn * 32 + ni * 8 + 2 * c;
            size_t o0 = (size_t)r * HID + col;
            size_t o1 = (size_t)(r + 8) * HID + col;
            float2 x0 = *reinterpret_cast<const float2*>(xres + o0);
            float2 x1 = *reinterpret_cast<const float2*>(xres + o1);
            *reinterpret_cast<float2*>(g_h1 + o0) =
                make_float2(x0.x + acc[mi][ni][0], x0.y + acc[mi][ni][1]);
            *reinterpret_cast<float2*>(g_h1 + o1) =
                make_float2(x1.x + acc[mi][ni][2], x1.y + acc[mi][ni][3]);
        }
    }
}

// MoE GEMM1: Hgu[slot] = Xp[slot] @ w_gate_up[e]   (rows_e x 768 x 3072)
__global__ void k_moe_gemm1(const float* __restrict__ Wgu) {
    int e = blockIdx.x >> 5, mb = blockIdx.x & 31, nb = blockIdx.y;
    int r0 = g_off[e];
    int rows_e = g_off[e + 1] - r0;
    int rbase = mb * 128;
    if (rbase >= rows_e) return;
    int rows = min(128, rows_e - rbase);
    float acc[4][4][4] = {};
    gemm_tf32_core(g_Xp + (size_t)(r0 + rbase) * HID, HID,
                   Wgu + (size_t)e * HID * (2 * FF) + nb * 128, 2 * FF, HID, rows, acc);
    int warp = threadIdx.x >> 5, lane = threadIdx.x & 31;
    int wm = warp >> 2, wn = warp & 3, g = lane >> 2, c = lane & 3;
    float* Cp = g_Hgu + (size_t)(r0 + rbase) * (2 * FF) + nb * 128;
#pragma unroll
    for (int mi = 0; mi < 4; mi++) {
#pragma unroll
        for (int ni = 0; ni < 4; ni++) {
            int rr = wm * 64 + mi * 16 + g;
            int col = wn * 32 + ni * 8 + 2 * c;
            if (rr < rows)
                *reinterpret_cast<float2*>(Cp + (size_t)rr * (2 * FF) + col) =
                    make_float2(acc[mi][ni][0], acc[mi][ni][1]);
            if (rr + 8 < rows)
                *reinterpret_cast<float2*>(Cp + (size_t)(rr + 8) * (2 * FF) + col) =
                    make_float2(acc[mi][ni][2], acc[mi][ni][3]);
        }
    }
}

// MoE GEMM2: Dn[slot] = Hact[slot] @ w_down[e]   (rows_e x 1536 x 768)
__global__ void k_moe_gemm2(const float* __restrict__ Wd) {
    int e = blockIdx.x >> 5, mb = blockIdx.x & 31, nb = blockIdx.y;
    int r0 = g_off[e];
    int rows_e = g_off[e + 1] - r0;
    int rbase = mb * 128;
    if (rbase >= rows_e) return;
    int rows = min(128, rows_e - rbase);
    float acc[4][4][4] = {};
    gemm_tf32_core(g_Hact + (size_t)(r0 + rbase) * FF, FF,
                   Wd + (size_t)e * FF * HID + nb * 128, HID, FF, rows, acc);
    int warp = threadIdx.x >> 5, lane = threadIdx.x & 31;
    int wm = warp >> 2, wn = warp & 3, g = lane >> 2, c = lane & 3;
    float* Cp = g_Dn + (size_t)(r0 + rbase) * HID + nb * 128;
#pragma unroll
    for (int mi = 0; mi < 4; mi++) {
#pragma unroll
        for (int ni = 0; ni < 4; ni++) {
            int rr = wm * 64 + mi * 16 + g;
            int col = wn * 32 + ni * 8 + 2 * c;
            if (rr < rows)
                *reinterpret_cast<float2*>(Cp + (size_t)rr * HID + col) =
                    make_float2(acc[mi][ni][0], acc[mi][ni][1]);
            if (rr + 8 < rows)
                *reinterpret_cast<float2*>(Cp + (size_t)(rr + 8) * HID + col) =
                    make_float2(acc[mi][ni][2], acc[mi][ni][3]);
        }
    }
}

// ---------------------------------------------------------------------------
// RoPE + split into head-major Q/K/V
// ---------------------------------------------------------------------------
__global__ void k_rope(void) {
    int s = blockIdx.x;
    int p = threadIdx.x;
    const float* row = g_qkv + (size_t)s * QKVC;
    if (p < 384) {
        int h = p >> 5, i = p & 31;
        float v0 = row[h * HD + 2 * i];
        float v1 = row[h * HD + 2 * i + 1];
        float inv = powf(10000.f, -(float)(2 * i) / (float)HD);
        float ang = (float)s * inv;
        float sn, cs;
        sincosf(ang, &sn, &cs);
        float* dst = g_Q + ((size_t)h * SEQ + s) * HD;
        dst[2 * i]     = v0 * cs - v1 * sn;
        dst[2 * i + 1] = v0 * sn + v1 * cs;
    } else if (p < 480) {
        int q = p - 384;
        int h = q >> 5, i = q & 31;
        float v0 = row[NQ * HD + h * HD + 2 * i];
        float v1 = row[NQ * HD + h * HD + 2 * i + 1];
        float inv = powf(10000.f, -(float)(2 * i) / (float)HD);
        float ang = (float)s * inv;
        float sn, cs;
        sincosf(ang, &sn, &cs);
        float* dst = g_K + ((size_t)h * SEQ + s) * HD;
        dst[2 * i]     = v0 * cs - v1 * sn;
        dst[2 * i + 1] = v0 * sn + v1 * cs;
    } else {
        int q = p - 480;
        int h = q >> 5, i = q & 31;
        float* dst = g_V + ((size_t)h * SEQ + s) * HD;
        dst[2 * i]     = row[(NQ + NKV) * HD + h * HD + 2 * i];
        dst[2 * i + 1] = row[(NQ + NKV) * HD + h * HD + 2 * i + 1];
    }
}

// ---------------------------------------------------------------------------
// Flash attention, fp32, parallel softmax (4 lanes/row)
// ---------------------------------------------------------------------------
#define ATT_SMEM_FLOATS (64 * 68 * 3 + 64 * 64 + 64 * 65 + 64 * 3)

__global__ void k_attn(void) {
    extern __shared__ float sm[];
    float* Qt   = sm;                 // [64 d][68]
    float* Kt   = Qt + 64 * 68;       // [64 d][68]
    float* Pt   = Kt + 64 * 68;       // [64 j][68]
    float* Vs   = Pt + 64 * 68;       // [64 j][64]
    float* Sm   = Vs + 64 * 64;       // [64 i][65]
    float* mrow = Sm + 64 * 65;
    float* lrow = mrow + 64;
    float* arow = lrow + 64;

    int qb = blockIdx.x, h = blockIdx.y;
    int kvh = h >> 2;
    int tid = threadIdx.x, tx = tid & 15, ty = tid >> 4;

    const float* Qb = g_Q + ((size_t)h * SEQ + qb * 64) * HD;
    for (int e = tid; e < 4096; e += 256) {
        int r = e >> 6, d = e & 63;
        Qt[d * 68 + r] = Qb[r * HD + d] * 0.125f;
    }
    if (tid < 64) { mrow[tid] = -1e30f; lrow[tid] = 0.f; }

    float acc[4][4] = {};
    for (int kb = 0; kb <= qb; kb++) {
        const float* Kb = g_K + ((size_t)kvh * SEQ + kb * 64) * HD;
        const float* Vb = g_V + ((size_t)kvh * SEQ + kb * 64) * HD;
        __syncthreads();
        for (int e = tid; e < 4096; e += 256) {
            int r = e >> 6, d = e & 63;
            Kt[d * 68 + r] = Kb[r * HD + d];
            Vs[e] = Vb[e];
        }
        __syncthreads();

        float s[4][4] = {};
#pragma unroll 8
        for (int d = 0; d < 64; d++) {
            float4 qa = *reinterpret_cast<const float4*>(&Qt[d * 68 + ty * 4]);
            float4 ka = *reinterpret_cast<const float4*>(&Kt[d * 68 + tx * 4]);
            float qr[4] = {qa.x, qa.y, qa.z, qa.w};
            float kr[4] = {ka.x, ka.y, ka.z, ka.w};
#pragma unroll
            for (int r = 0; r < 4; r++)
#pragma unroll
                for (int c = 0; c < 4; c++) s[r][c] += qr[r] * kr[c];
        }
        int grb = qb * 64 + ty * 4, gcb = kb * 64 + tx * 4;
#pragma unroll
        for (int r = 0; r < 4; r++)
#pragma unroll
            for (int c = 0; c < 4; c++)
                Sm[(ty * 4 + r) * 65 + tx * 4 + c] =
                    (gcb + c <= grb + r) ? s[r][c] : -1e30f;
        __syncthreads();

        // softmax: 4 lanes per row
        {
            int i  = tid >> 2;
            int jq = (tid & 3) * 16;
            float mx = -1e30f;
#pragma unroll
            for (int j = 0; j < 16; j++) mx = fmaxf(mx, Sm[i * 65 + jq + j]);
            mx = fmaxf(mx, __shfl_xor_sync(0xffffffffu, mx, 1));
            mx = fmaxf(mx, __shfl_xor_sync(0xffffffffu, mx, 2));
            float mold = mrow[i];
            mx = fmaxf(mx, mold);
            float sum = 0.f;
#pragma unroll
            for (int j = 0; j < 16; j++) {
                float p = __expf(Sm[i * 65 + jq + j] - mx);
                Pt[(jq + j) * 68 + i] = p;
                sum += p;
            }
            sum += __shfl_xor_sync(0xffffffffu, sum, 1);
            sum += __shfl_xor_sync(0xffffffffu, sum, 2);
            if ((tid & 3) == 0) {
                float al = __expf(mold - mx);
                lrow[i] = lrow[i] * al + sum;
                mrow[i] = mx;
                arow[i] = al;
            }
        }
        __syncthreads();

#pragma unroll
        for (int r = 0; r < 4; r++) {
            float al = arow[ty * 4 + r];
#pragma unroll
            for (int c = 0; c < 4; c++) acc[r][c] *= al;
        }
#pragma unroll 8
        for (int j = 0; j < 64; j++) {
            float4 pa = *reinterpret_cast<const float4*>(&Pt[j * 68 + ty * 4]);
            float4 va = *reinterpret_cast<const float4*>(&Vs[j * 64 + tx * 4]);
            float pr[4] = {pa.x, pa.y, pa.z, pa.w};
            float vr[4] = {va.x, va.y, va.z, va.w};
#pragma unroll
            for (int r = 0; r < 4; r++)
#pragma unroll
                for (int c = 0; c < 4; c++) acc[r][c] += pr[r] * vr[c];
        }
    }

#pragma unroll
    for (int r = 0; r < 4; r++) {
        float inv = 1.f / lrow[ty * 4 + r];
        int grow = qb * 64 + ty * 4 + r;
        float4 o = make_float4(acc[r][0] * inv, acc[r][1] * inv,
                               acc[r][2] * inv, acc[r][3] * inv);
        *reinterpret_cast<float4*>(g_attn + (size_t)grow * HID + h * HD + tx * 4) = o;
    }
}

// ---------------------------------------------------------------------------
// MoE routing / permutation (fp32 router — expert picks must not flip)
// ---------------------------------------------------------------------------
__global__ void k_reset(void) {
    if (threadIdx.x < NE) {
        g_cnt[threadIdx.x] = 0;
        g_cur[threadIdx.x] = 0;
    }
}

__global__ void k_router(const float* __restrict__ Wr) {
    int t = blockIdx.x;
    int w = threadIdx.x >> 5, lane = threadIdx.x & 31;
    __shared__ float lg[NE];
    const float* xr = g_xn2 + (size_t)t * HID;
    float s = 0.f;
    for (int k = lane; k < HID; k += 32) s += xr[k] * Wr[k * NE + w];
#pragma unroll
    for (int o = 16; o > 0; o >>= 1) s += __shfl_xor_sync(0xffffffffu, s, o);
    if (lane == 0) lg[w] = s;
    __syncthreads();
    if (threadIdx.x == 0) {
        int b0 = 0;
        float v0 = lg[0];
        for (int e = 1; e < NE; e++)
            if (lg[e] > v0) { v0 = lg[e]; b0 = e; }
        int b1 = -1;
        float v1 = -3e38f;
        for (int e = 0; e < NE; e++)
            if (e != b0 && lg[e] > v1) { v1 = lg[e]; b1 = e; }
        float w0 = 1.f / (1.f + __expf(v1 - v0));
        g_eid[2 * t] = b0;
        g_eid[2 * t + 1] = b1;
        g_ew[2 * t] = w0;
        g_ew[2 * t + 1] = 1.f - w0;
        atomicAdd(&g_cnt[b0], 1);
        atomicAdd(&g_cnt[b1], 1);
    }
}

__global__ void k_scan(void) {
    if (threadIdx.x == 0) {
        int a = 0;
        for (int e = 0; e < NE; e++) {
            g_off[e] = a;
            a += g_cnt[e];
        }
        g_off[NE] = a;
    }
}

__global__ void k_scatter(void) {
    int t = blockIdx.x * blockDim.x + threadIdx.x;
    if (t >= SEQ) return;
#pragma unroll
    for (int slot = 0; slot < 2; slot++) {
        int e = g_eid[2 * t + slot];
        int pos = g_off[e] + atomicAdd(&g_cur[e], 1);
        g_ptok[pos] = t;
        g_tslot[2 * t + slot] = pos;
    }
}

__global__ void k_gather(void) {
    int pos = blockIdx.x;
    int tok = g_ptok[pos];
    const float4* src = reinterpret_cast<const float4*>(g_xn2 + (size_t)tok * HID);
    float4* dst = reinterpret_cast<float4*>(g_Xp + (size_t)pos * HID);
    dst[threadIdx.x] = src[threadIdx.x];
}

__global__ void k_silu(void) {
    int idx = blockIdx.x * blockDim.x + threadIdx.x;
    const int total = SLOTS * FF;
    if (idx >= total) return;
    int pos = idx / FF, j = idx - pos * FF;
    float g = g_Hgu[(size_t)pos * (2 * FF) + j];
    float u = g_Hgu[(size_t)pos * (2 * FF) + FF + j];
    float sg = g / (1.f + __expf(-g));
    g_Hact[idx] = sg * u;
}

__global__ void k_combine(float* __restrict__ out) {
    int t = blockIdx.x;
    int i = threadIdx.x;
    int p0 = g_tslot[2 * t], p1 = g_tslot[2 * t + 1];
    float w0 = g_ew[2 * t], w1 = g_ew[2 * t + 1];
    float4 a = reinterpret_cast<const float4*>(g_h1 + (size_t)t * HID)[i];
    float4 b = reinterpret_cast<const float4*>(g_Dn + (size_t)p0 * HID)[i];
    float4 c = reinterpret_cast<const float4*>(g_Dn + (size_t)p1 * HID)[i];
    float4 o = make_float4(a.x + w0 * b.x + w1 * c.x,
                           a.y + w0 * b.y + w1 * c.y,
                           a.z + w0 * b.z + w1 * c.z,
                           a.w + w0 * b.w + w1 * c.w);
    reinterpret_cast<float4*>(out + (size_t)t * HID)[i] = o;
}

// ---------------------------------------------------------------------------
// Launch
// ---------------------------------------------------------------------------
extern "C" void kernel_launch(void* const* d_in, const int* in_sizes, int n_in,
                              void* d_out, int out_size) {
    (void)in_sizes; (void)n_in; (void)out_size;
    const float* x        = (const float*)d_in[0];
    const float* norm1_w  = (const float*)d_in[1];
    const float* w_qkv    = (const float*)d_in[2];
    const float* w_out    = (const float*)d_in[3];
    const float* norm2_w  = (const float*)d_in[4];
    const float* w_router = (const float*)d_in[5];
    const float* w_gateup = (const float*)d_in[6];
    const float* w_down   = (const float*)d_in[7];
    float* out = (float*)d_out;

    const int att_smem = ATT_SMEM_FLOATS * (int)sizeof(float);
    cudaFuncSetAttribute(k_attn, cudaFuncAttributeMaxDynamicSharedMemorySize, att_smem);

    k_reset<<<1, 32>>>();
    k_rmsnorm1<<<SEQ, 256>>>(x, norm1_w);
    k_gemm_qkv<<<dim3(SEQ / 128, QKVC / 128), 256>>>(w_qkv);
    k_rope<<<SEQ, 576>>>();
    k_attn<<<dim3(SEQ / 64, NQ), 256, att_smem>>>();
    k_gemm_out<<<dim3(SEQ / 128, HID / 128), 256>>>(w_out, x);
    k_rmsnorm2<<<SEQ, 256>>>(norm2_w);
    k_router<<<SEQ, 512>>>(w_router);
    k_scan<<<1, 32>>>();
    k_scatter<<<(SEQ + 255) / 256, 256>>>();
    k_gather<<<SLOTS, 192>>>();
    k_moe_gemm1<<<dim3(NE * 32, (2 * FF) / 128), 256>>>(w_gateup);
    k_silu<<<(SLOTS * FF + 255) / 256, 256>>>();
    k_moe_gemm2<<<dim3(NE * 32, HID / 128), 256>>>(w_down);
    k_combine<<<SEQ, 192>>>(out);
}

// round 4
// speedup vs baseline: 2.1619x; 1.1824x over previous
#include <cuda_runtime.h>
#include <math.h>

// ---------------------------------------------------------------------------
// Constants
// ---------------------------------------------------------------------------
#define SEQ   2048
#define HID   768
#define NQ    12
#define NKV   3
#define HD    64
#define QKVC  1152          // (NQ + 2*NKV) * HD
#define NE    16
#define FF    1536
#define SLOTS 4096          // SEQ * TOPK

// ---------------------------------------------------------------------------
// Device scratch (globals only referenced from device code!)
// ---------------------------------------------------------------------------
__device__ float g_xn1[SEQ * HID];
__device__ float g_qkv[SEQ * QKVC];
__device__ float g_Q[NQ * SEQ * HD];
__device__ float g_K[NKV * SEQ * HD];
__device__ float g_V[NKV * SEQ * HD];
__device__ float g_attn[SEQ * HID];
__device__ float g_h1[SEQ * HID];
__device__ float g_xn2[SEQ * HID];
__device__ int   g_eid[SLOTS];
__device__ float g_ew[SLOTS];
__device__ int   g_cnt[NE];
__device__ int   g_off[NE + 1];
__device__ int   g_cur[NE];
__device__ int   g_ptok[SLOTS];
__device__ int   g_tslot[SLOTS];
__device__ float g_Xp[(size_t)SLOTS * HID];
__device__ float g_Hgu[(size_t)SLOTS * 2 * FF];
__device__ float g_Hact[(size_t)SLOTS * FF];
__device__ float g_Dn[(size_t)SLOTS * HID];

// ---------------------------------------------------------------------------
// TF32 helpers
// ---------------------------------------------------------------------------
__device__ __forceinline__ unsigned f2tf(float f) {
    unsigned u;
    asm("cvt.rna.tf32.f32 %0, %1;" : "=r"(u) : "f"(f));
    return u;
}

__device__ __forceinline__ void mma_tf32(float d[4], const unsigned a[4],
                                         const unsigned b[2]) {
    asm volatile(
        "mma.sync.aligned.m16n8k8.row.col.f32.tf32.tf32.f32 "
        "{%0,%1,%2,%3}, {%4,%5,%6,%7}, {%8,%9}, {%0,%1,%2,%3};"
        : "+f"(d[0]), "+f"(d[1]), "+f"(d[2]), "+f"(d[3])
        : "r"(a[0]), "r"(a[1]), "r"(a[2]), "r"(a[3]),
          "r"(b[0]), "r"(b[1]));
}

// ---------------------------------------------------------------------------
// RMSNorm
// ---------------------------------------------------------------------------
__device__ __forceinline__ void rmsnorm_row(const float* __restrict__ xr,
                                            const float* __restrict__ w,
                                            float* __restrict__ yr) {
    float s = 0.f;
    for (int i = threadIdx.x; i < HID; i += 256) {
        float v = xr[i];
        s += v * v;
    }
    __shared__ float red[256];
    red[threadIdx.x] = s;
    __syncthreads();
    for (int o = 128; o > 0; o >>= 1) {
        if (threadIdx.x < o) red[threadIdx.x] += red[threadIdx.x + o];
        __syncthreads();
    }
    float scale = rsqrtf(red[0] / (float)HID + 1e-6f);
    for (int i = threadIdx.x; i < HID; i += 256)
        yr[i] = xr[i] * scale * w[i];
}

__global__ void k_rmsnorm1(const float* __restrict__ x, const float* __restrict__ w) {
    int row = blockIdx.x;
    rmsnorm_row(x + (size_t)row * HID, w, g_xn1 + (size_t)row * HID);
}

__global__ void k_rmsnorm2(const float* __restrict__ w) {
    int row = blockIdx.x;
    rmsnorm_row(g_h1 + (size_t)row * HID, w, g_xn2 + (size_t)row * HID);
}

// ---------------------------------------------------------------------------
// TF32 tensor-core GEMM: 128x128 tile, 256 threads (8 warps, 2x4),
// warp tile 64x32 = 4x4 m16n8k8 fragments, K-step 16.
// ---------------------------------------------------------------------------
__device__ __forceinline__ void gemm_tf32_core(const float* __restrict__ A, int lda,
                                               const float* __restrict__ B, int ldb,
                                               int K, int rows, float acc[4][4][4]) {
    __shared__ unsigned sA[128][20];   // stride-20 pad: conflict-free frag loads
    __shared__ unsigned sB[16][132];
    int tid  = threadIdx.x;
    int warp = tid >> 5, lane = tid & 31;
    int wm = warp >> 2;                // 0..1
    int wn = warp & 3;                 // 0..3
    int g  = lane >> 2;                // 0..7
    int c  = lane & 3;                 // 0..3

    for (int k0 = 0; k0 < K; k0 += 16) {
        // stage A 128x16 (guarded, converted to tf32)
#pragma unroll
        for (int it = 0; it < 2; it++) {
            int idx = tid + it * 256;
            int row = idx >> 2;
            int kq  = (idx & 3) * 4;
            float4 v = make_float4(0.f, 0.f, 0.f, 0.f);
            if (row < rows)
                v = *reinterpret_cast<const float4*>(A + (size_t)row * lda + k0 + kq);
            sA[row][kq + 0] = f2tf(v.x);
            sA[row][kq + 1] = f2tf(v.y);
            sA[row][kq + 2] = f2tf(v.z);
            sA[row][kq + 3] = f2tf(v.w);
        }
        // stage B 16x128 (coalesced)
#pragma unroll
        for (int it = 0; it < 2; it++) {
            int idx = tid + it * 256;
            int kr  = idx >> 5;         // 0..15
            int c4  = (idx & 31) * 4;
            float4 v = *reinterpret_cast<const float4*>(B + (size_t)(k0 + kr) * ldb + c4);
            sB[kr][c4 + 0] = f2tf(v.x);
            sB[kr][c4 + 1] = f2tf(v.y);
            sB[kr][c4 + 2] = f2tf(v.z);
            sB[kr][c4 + 3] = f2tf(v.w);
        }
        __syncthreads();
#pragma unroll
        for (int kk = 0; kk < 16; kk += 8) {
            unsigned af[4][4];
#pragma unroll
            for (int mi = 0; mi < 4; mi++) {
                int m = wm * 64 + mi * 16;
                af[mi][0] = sA[m + g][kk + c];
                af[mi][1] = sA[m + g + 8][kk + c];
                af[mi][2] = sA[m + g][kk + c + 4];
                af[mi][3] = sA[m + g + 8][kk + c + 4];
            }
#pragma unroll
            for (int ni = 0; ni < 4; ni++) {
                int n = wn * 32 + ni * 8 + g;
                unsigned bf[2];
                bf[0] = sB[kk + c][n];
                bf[1] = sB[kk + c + 4][n];
#pragma unroll
                for (int mi = 0; mi < 4; mi++)
                    mma_tf32(acc[mi][ni], af[mi], bf);
            }
        }
        __syncthreads();
    }
}

// QKV projection: g_qkv = g_xn1 @ w_qkv   (2048 x 768 x 1152)
__global__ void k_gemm_qkv(const float* __restrict__ W) {
    int mb = blockIdx.x, nb = blockIdx.y;
    float acc[4][4][4] = {};
    gemm_tf32_core(g_xn1 + (size_t)mb * 128 * HID, HID, W + nb * 128, QKVC, HID, 128, acc);
    int warp = threadIdx.x >> 5, lane = threadIdx.x & 31;
    int wm = warp >> 2, wn = warp & 3, g = lane >> 2, c = lane & 3;
#pragma unroll
    for (int mi = 0; mi < 4; mi++) {
#pragma unroll
        for (int ni = 0; ni < 4; ni++) {
            int r = mb * 128 + wm * 64 + mi * 16 + g;
            int col = nb * 128 + wn * 32 + ni * 8 + 2 * c;
            *reinterpret_cast<float2*>(g_qkv + (size_t)r * QKVC + col) =
                make_float2(acc[mi][ni][0], acc[mi][ni][1]);
            *reinterpret_cast<float2*>(g_qkv + (size_t)(r + 8) * QKVC + col) =
                make_float2(acc[mi][ni][2], acc[mi][ni][3]);
        }
    }
}

// Out projection + residual: g_h1 = x + g_attn @ w_out   (2048 x 768 x 768)
__global__ void k_gemm_out(const float* __restrict__ W, const float* __restrict__ xres) {
    int mb = blockIdx.x, nb = blockIdx.y;
    float acc[4][4][4] = {};
    gemm_tf32_core(g_attn + (size_t)mb * 128 * HID, HID, W + nb * 128, HID, HID, 128, acc);
    int warp = threadIdx.x >> 5, lane = threadIdx.x & 31;
    int wm = warp >> 2, wn = warp & 3, g = lane >> 2, c = lane & 3;
#pragma unroll
    for (int mi = 0; mi < 4; mi++) {
#pragma unroll
        for (int ni = 0; ni < 4; ni++) {
            int r = mb * 128 + wm * 64 + mi * 16 + g;
            int col = nb * 128 + wn * 32 + ni * 8 + 2 * c;
            size_t o0 = (size_t)r * HID + col;
            size_t o1 = (size_t)(r + 8) * HID + col;
            float2 x0 = *reinterpret_cast<const float2*>(xres + o0);
            float2 x1 = *reinterpret_cast<const float2*>(xres + o1);
            *reinterpret_cast<float2*>(g_h1 + o0) =
                make_float2(x0.x + acc[mi][ni][0], x0.y + acc[mi][ni][1]);
            *reinterpret_cast<float2*>(g_h1 + o1) =
                make_float2(x1.x + acc[mi][ni][2], x1.y + acc[mi][ni][3]);
        }
    }
}

// MoE GEMM1: Hgu[slot] = Xp[slot] @ w_gate_up[e]   (rows_e x 768 x 3072)
__global__ void k_moe_gemm1(const float* __restrict__ Wgu) {
    int e = blockIdx.x >> 5, mb = blockIdx.x & 31, nb = blockIdx.y;
    int r0 = g_off[e];
    int rows_e = g_off[e + 1] - r0;
    int rbase = mb * 128;
    if (rbase >= rows_e) return;
    int rows = min(128, rows_e - rbase);
    float acc[4][4][4] = {};
    gemm_tf32_core(g_Xp + (size_t)(r0 + rbase) * HID, HID,
                   Wgu + (size_t)e * HID * (2 * FF) + nb * 128, 2 * FF, HID, rows, acc);
    int warp = threadIdx.x >> 5, lane = threadIdx.x & 31;
    int wm = warp >> 2, wn = warp & 3, g = lane >> 2, c = lane & 3;
    float* Cp = g_Hgu + (size_t)(r0 + rbase) * (2 * FF) + nb * 128;
#pragma unroll
    for (int mi = 0; mi < 4; mi++) {
#pragma unroll
        for (int ni = 0; ni < 4; ni++) {
            int rr = wm * 64 + mi * 16 + g;
            int col = wn * 32 + ni * 8 + 2 * c;
            if (rr < rows)
                *reinterpret_cast<float2*>(Cp + (size_t)rr * (2 * FF) + col) =
                    make_float2(acc[mi][ni][0], acc[mi][ni][1]);
            if (rr + 8 < rows)
                *reinterpret_cast<float2*>(Cp + (size_t)(rr + 8) * (2 * FF) + col) =
                    make_float2(acc[mi][ni][2], acc[mi][ni][3]);
        }
    }
}

// MoE GEMM2: Dn[slot] = Hact[slot] @ w_down[e]   (rows_e x 1536 x 768)
__global__ void k_moe_gemm2(const float* __restrict__ Wd) {
    int e = blockIdx.x >> 5, mb = blockIdx.x & 31, nb = blockIdx.y;
    int r0 = g_off[e];
    int rows_e = g_off[e + 1] - r0;
    int rbase = mb * 128;
    if (rbase >= rows_e) return;
    int rows = min(128, rows_e - rbase);
    float acc[4][4][4] = {};
    gemm_tf32_core(g_Hact + (size_t)(r0 + rbase) * FF, FF,
                   Wd + (size_t)e * FF * HID + nb * 128, HID, FF, rows, acc);
    int warp = threadIdx.x >> 5, lane = threadIdx.x & 31;
    int wm = warp >> 2, wn = warp & 3, g = lane >> 2, c = lane & 3;
    float* Cp = g_Dn + (size_t)(r0 + rbase) * HID + nb * 128;
#pragma unroll
    for (int mi = 0; mi < 4; mi++) {
#pragma unroll
        for (int ni = 0; ni < 4; ni++) {
            int rr = wm * 64 + mi * 16 + g;
            int col = wn * 32 + ni * 8 + 2 * c;
            if (rr < rows)
                *reinterpret_cast<float2*>(Cp + (size_t)rr * HID + col) =
                    make_float2(acc[mi][ni][0], acc[mi][ni][1]);
            if (rr + 8 < rows)
                *reinterpret_cast<float2*>(Cp + (size_t)(rr + 8) * HID + col) =
                    make_float2(acc[mi][ni][2], acc[mi][ni][3]);
        }
    }
}

// ---------------------------------------------------------------------------
// RoPE + split into head-major Q/K/V
// ---------------------------------------------------------------------------
__global__ void k_rope(void) {
    int s = blockIdx.x;
    int p = threadIdx.x;
    const float* row = g_qkv + (size_t)s * QKVC;
    if (p < 384) {
        int h = p >> 5, i = p & 31;
        float v0 = row[h * HD + 2 * i];
        float v1 = row[h * HD + 2 * i + 1];
        float inv = powf(10000.f, -(float)(2 * i) / (float)HD);
        float ang = (float)s * inv;
        float sn, cs;
        sincosf(ang, &sn, &cs);
        float* dst = g_Q + ((size_t)h * SEQ + s) * HD;
        dst[2 * i]     = v0 * cs - v1 * sn;
        dst[2 * i + 1] = v0 * sn + v1 * cs;
    } else if (p < 480) {
        int q = p - 384;
        int h = q >> 5, i = q & 31;
        float v0 = row[NQ * HD + h * HD + 2 * i];
        float v1 = row[NQ * HD + h * HD + 2 * i + 1];
        float inv = powf(10000.f, -(float)(2 * i) / (float)HD);
        float ang = (float)s * inv;
        float sn, cs;
        sincosf(ang, &sn, &cs);
        float* dst = g_K + ((size_t)h * SEQ + s) * HD;
        dst[2 * i]     = v0 * cs - v1 * sn;
        dst[2 * i + 1] = v0 * sn + v1 * cs;
    } else {
        int q = p - 480;
        int h = q >> 5, i = q & 31;
        float* dst = g_V + ((size_t)h * SEQ + s) * HD;
        dst[2 * i]     = row[(NQ + NKV) * HD + h * HD + 2 * i];
        dst[2 * i + 1] = row[(NQ + NKV) * HD + h * HD + 2 * i + 1];
    }
}

// ---------------------------------------------------------------------------
// Flash attention, TF32 tensor cores. Block = (64-query tile, head).
// 256 threads = 8 warps (2x4). Warp tiles 32x16 for both S=QK^T and O=PV.
// All smem operands row-major with stride 68 (68 % 32 == 4 -> A/B frag
// loads are bank-conflict-free: 4g+c is a permutation of 0..31).
// ---------------------------------------------------------------------------
#define ATT_SMEM_BYTES ((4 * 64 * 68 + 64 * 65 + 3 * 64) * 4)

__global__ void k_attn(void) {
    extern __shared__ unsigned smu[];
    unsigned* uQ = smu;               // [64][68] tf32
    unsigned* uK = uQ + 64 * 68;      // [64][68] tf32
    unsigned* uV = uK + 64 * 68;      // [64][68] tf32
    unsigned* uP = uV + 64 * 68;      // [64][68] tf32
    float* Sm    = (float*)(uP + 64 * 68);  // [64][65]
    float* mrow  = Sm + 64 * 65;
    float* lrow  = mrow + 64;
    float* arow  = lrow + 64;

    int qb = gridDim.x - 1 - blockIdx.x;   // heavy tiles first (load balance)
    int h  = blockIdx.y;
    int kvh = h >> 2;                      // REP = 4
    int tid = threadIdx.x;
    int warp = tid >> 5, lane = tid & 31;
    int wm = warp >> 2, wn = warp & 3;     // 2 x 4 warp grid
    int g  = lane >> 2, c = lane & 3;

    const float* Qb = g_Q + ((size_t)h * SEQ + qb * 64) * HD;
    for (int e = tid; e < 4096; e += 256) {
        int r = e >> 6, d = e & 63;
        uQ[r * 68 + d] = f2tf(Qb[r * HD + d] * 0.125f);  // 1/sqrt(64)
    }
    if (tid < 64) { mrow[tid] = -1e30f; lrow[tid] = 0.f; }

    float oacc[2][2][4] = {};
    for (int kb = 0; kb <= qb; kb++) {
        const float* Kb = g_K + ((size_t)kvh * SEQ + kb * 64) * HD;
        const float* Vb = g_V + ((size_t)kvh * SEQ + kb * 64) * HD;
        __syncthreads();                   // uK/uV free (prev PV done)
        for (int e = tid; e < 4096; e += 256) {
            int r = e >> 6, d = e & 63;
            uK[r * 68 + d] = f2tf(Kb[r * HD + d]);
            uV[r * 68 + d] = f2tf(Vb[r * HD + d]);
        }
        __syncthreads();

        // ---- S = Q @ K^T (64x64), warp tile 32x16 ----
        float sacc[2][2][4] = {};
#pragma unroll
        for (int kk = 0; kk < 64; kk += 8) {
            unsigned af[2][4];
#pragma unroll
            for (int mi = 0; mi < 2; mi++) {
                int m = wm * 32 + mi * 16;
                af[mi][0] = uQ[(m + g) * 68 + kk + c];
                af[mi][1] = uQ[(m + g + 8) * 68 + kk + c];
                af[mi][2] = uQ[(m + g) * 68 + kk + c + 4];
                af[mi][3] = uQ[(m + g + 8) * 68 + kk + c + 4];
            }
#pragma unroll
            for (int ni = 0; ni < 2; ni++) {
                int n = wn * 16 + ni * 8 + g;
                unsigned bf[2];
                bf[0] = uK[n * 68 + kk + c];
                bf[1] = uK[n * 68 + kk + c + 4];
#pragma unroll
                for (int mi = 0; mi < 2; mi++)
                    mma_tf32(sacc[mi][ni], af[mi], bf);
            }
        }
        // write masked S to smem
        bool diag = (kb == qb);
#pragma unroll
        for (int mi = 0; mi < 2; mi++) {
#pragma unroll
            for (int ni = 0; ni < 2; ni++) {
                int r0 = wm * 32 + mi * 16 + g;
                int cl = wn * 16 + ni * 8 + 2 * c;
                float v0 = sacc[mi][ni][0], v1 = sacc[mi][ni][1];
                float v2 = sacc[mi][ni][2], v3 = sacc[mi][ni][3];
                if (diag) {
                    if (cl > r0)     v0 = -1e30f;
                    if (cl + 1 > r0) v1 = -1e30f;
                    if (cl > r0 + 8)     v2 = -1e30f;
                    if (cl + 1 > r0 + 8) v3 = -1e30f;
                }
                Sm[r0 * 65 + cl]           = v0;
                Sm[r0 * 65 + cl + 1]       = v1;
                Sm[(r0 + 8) * 65 + cl]     = v2;
                Sm[(r0 + 8) * 65 + cl + 1] = v3;
            }
        }
        __syncthreads();

        // ---- online softmax: 4 lanes per row, write P (tf32) row-major ----
        {
            int i  = tid >> 2;
            int jq = (tid & 3) * 16;
            float mx = -1e30f;
#pragma unroll
            for (int j = 0; j < 16; j++) mx = fmaxf(mx, Sm[i * 65 + jq + j]);
            mx = fmaxf(mx, __shfl_xor_sync(0xffffffffu, mx, 1));
            mx = fmaxf(mx, __shfl_xor_sync(0xffffffffu, mx, 2));
            float mold = mrow[i];
            mx = fmaxf(mx, mold);
            float sum = 0.f;
#pragma unroll
            for (int j = 0; j < 16; j++) {
                float p = __expf(Sm[i * 65 + jq + j] - mx);
                uP[i * 68 + jq + j] = f2tf(p);
                sum += p;
            }
            sum += __shfl_xor_sync(0xffffffffu, sum, 1);
            sum += __shfl_xor_sync(0xffffffffu, sum, 2);
            if ((tid & 3) == 0) {
                float al = __expf(mold - mx);
                lrow[i] = lrow[i] * al + sum;
                mrow[i] = mx;
                arow[i] = al;
            }
        }
        __syncthreads();

        // ---- rescale O accumulators by alpha ----
#pragma unroll
        for (int mi = 0; mi < 2; mi++) {
            float a0 = arow[wm * 32 + mi * 16 + g];
            float a1 = arow[wm * 32 + mi * 16 + g + 8];
#pragma unroll
            for (int ni = 0; ni < 2; ni++) {
                oacc[mi][ni][0] *= a0;
                oacc[mi][ni][1] *= a0;
                oacc[mi][ni][2] *= a1;
                oacc[mi][ni][3] *= a1;
            }
        }

        // ---- O += P @ V (64x64) ----
#pragma unroll
        for (int kk = 0; kk < 64; kk += 8) {
            unsigned af[2][4];
#pragma unroll
            for (int mi = 0; mi < 2; mi++) {
                int m = wm * 32 + mi * 16;
                af[mi][0] = uP[(m + g) * 68 + kk + c];
                af[mi][1] = uP[(m + g + 8) * 68 + kk + c];
                af[mi][2] = uP[(m + g) * 68 + kk + c + 4];
                af[mi][3] = uP[(m + g + 8) * 68 + kk + c + 4];
            }
#pragma unroll
            for (int ni = 0; ni < 2; ni++) {
                int n = wn * 16 + ni * 8 + g;
                unsigned bf[2];
                bf[0] = uV[(kk + c) * 68 + n];
                bf[1] = uV[(kk + c + 4) * 68 + n];
#pragma unroll
                for (int mi = 0; mi < 2; mi++)
                    mma_tf32(oacc[mi][ni], af[mi], bf);
            }
        }
    }

    // ---- epilogue: O / l, write head-interleaved ----
    __syncthreads();
#pragma unroll
    for (int mi = 0; mi < 2; mi++) {
        int rl0 = wm * 32 + mi * 16 + g;
        float i0 = 1.f / lrow[rl0];
        float i1 = 1.f / lrow[rl0 + 8];
        int gr0 = qb * 64 + rl0;
#pragma unroll
        for (int ni = 0; ni < 2; ni++) {
            int col = h * HD + wn * 16 + ni * 8 + 2 * c;
            *reinterpret_cast<float2*>(g_attn + (size_t)gr0 * HID + col) =
                make_float2(oacc[mi][ni][0] * i0, oacc[mi][ni][1] * i0);
            *reinterpret_cast<float2*>(g_attn + (size_t)(gr0 + 8) * HID + col) =
                make_float2(oacc[mi][ni][2] * i1, oacc[mi][ni][3] * i1);
        }
    }
}

// ---------------------------------------------------------------------------
// MoE routing / permutation (fp32 router — expert picks must not flip)
// ---------------------------------------------------------------------------
__global__ void k_reset(void) {
    if (threadIdx.x < NE) {
        g_cnt[threadIdx.x] = 0;
        g_cur[threadIdx.x] = 0;
    }
}

__global__ void k_router(const float* __restrict__ Wr) {
    int t = blockIdx.x;
    int w = threadIdx.x >> 5, lane = threadIdx.x & 31;
    __shared__ float lg[NE];
    const float* xr = g_xn2 + (size_t)t * HID;
    float s = 0.f;
    for (int k = lane; k < HID; k += 32) s += xr[k] * Wr[k * NE + w];
#pragma unroll
    for (int o = 16; o > 0; o >>= 1) s += __shfl_xor_sync(0xffffffffu, s, o);
    if (lane == 0) lg[w] = s;
    __syncthreads();
    if (threadIdx.x == 0) {
        int b0 = 0;
        float v0 = lg[0];
        for (int e = 1; e < NE; e++)
            if (lg[e] > v0) { v0 = lg[e]; b0 = e; }
        int b1 = -1;
        float v1 = -3e38f;
        for (int e = 0; e < NE; e++)
            if (e != b0 && lg[e] > v1) { v1 = lg[e]; b1 = e; }
        float w0 = 1.f / (1.f + __expf(v1 - v0));
        g_eid[2 * t] = b0;
        g_eid[2 * t + 1] = b1;
        g_ew[2 * t] = w0;
        g_ew[2 * t + 1] = 1.f - w0;
        atomicAdd(&g_cnt[b0], 1);
        atomicAdd(&g_cnt[b1], 1);
    }
}

__global__ void k_scan(void) {
    if (threadIdx.x == 0) {
        int a = 0;
        for (int e = 0; e < NE; e++) {
            g_off[e] = a;
            a += g_cnt[e];
        }
        g_off[NE] = a;
    }
}

__global__ void k_scatter(void) {
    int t = blockIdx.x * blockDim.x + threadIdx.x;
    if (t >= SEQ) return;
#pragma unroll
    for (int slot = 0; slot < 2; slot++) {
        int e = g_eid[2 * t + slot];
        int pos = g_off[e] + atomicAdd(&g_cur[e], 1);
        g_ptok[pos] = t;
        g_tslot[2 * t + slot] = pos;
    }
}

__global__ void k_gather(void) {
    int pos = blockIdx.x;
    int tok = g_ptok[pos];
    const float4* src = reinterpret_cast<const float4*>(g_xn2 + (size_t)tok * HID);
    float4* dst = reinterpret_cast<float4*>(g_Xp + (size_t)pos * HID);
    dst[threadIdx.x] = src[threadIdx.x];
}

__global__ void k_silu(void) {
    int idx = blockIdx.x * blockDim.x + threadIdx.x;
    const int total = SLOTS * FF;
    if (idx >= total) return;
    int pos = idx / FF, j = idx - pos * FF;
    float g = g_Hgu[(size_t)pos * (2 * FF) + j];
    float u = g_Hgu[(size_t)pos * (2 * FF) + FF + j];
    float sg = g / (1.f + __expf(-g));
    g_Hact[idx] = sg * u;
}

__global__ void k_combine(float* __restrict__ out) {
    int t = blockIdx.x;
    int i = threadIdx.x;
    int p0 = g_tslot[2 * t], p1 = g_tslot[2 * t + 1];
    float w0 = g_ew[2 * t], w1 = g_ew[2 * t + 1];
    float4 a = reinterpret_cast<const float4*>(g_h1 + (size_t)t * HID)[i];
    float4 b = reinterpret_cast<const float4*>(g_Dn + (size_t)p0 * HID)[i];
    float4 c = reinterpret_cast<const float4*>(g_Dn + (size_t)p1 * HID)[i];
    float4 o = make_float4(a.x + w0 * b.x + w1 * c.x,
                           a.y + w0 * b.y + w1 * c.y,
                           a.z + w0 * b.z + w1 * c.z,
                           a.w + w0 * b.w + w1 * c.w);
    reinterpret_cast<float4*>(out + (size_t)t * HID)[i] = o;
}

// ---------------------------------------------------------------------------
// Launch
// ---------------------------------------------------------------------------
extern "C" void kernel_launch(void* const* d_in, const int* in_sizes, int n_in,
                              void* d_out, int out_size) {
    (void)in_sizes; (void)n_in; (void)out_size;
    const float* x        = (const float*)d_in[0];
    const float* norm1_w  = (const float*)d_in[1];
    const float* w_qkv    = (const float*)d_in[2];
    const float* w_out    = (const float*)d_in[3];
    const float* norm2_w  = (const float*)d_in[4];
    const float* w_router = (const float*)d_in[5];
    const float* w_gateup = (const float*)d_in[6];
    const float* w_down   = (const float*)d_in[7];
    float* out = (float*)d_out;

    cudaFuncSetAttribute(k_attn, cudaFuncAttributeMaxDynamicSharedMemorySize,
                         ATT_SMEM_BYTES);

    k_reset<<<1, 32>>>();
    k_rmsnorm1<<<SEQ, 256>>>(x, norm1_w);
    k_gemm_qkv<<<dim3(SEQ / 128, QKVC / 128), 256>>>(w_qkv);
    k_rope<<<SEQ, 576>>>();
    k_attn<<<dim3(SEQ / 64, NQ), 256, ATT_SMEM_BYTES>>>();
    k_gemm_out<<<dim3(SEQ / 128, HID / 128), 256>>>(w_out, x);
    k_rmsnorm2<<<SEQ, 256>>>(norm2_w);
    k_router<<<SEQ, 512>>>(w_router);
    k_scan<<<1, 32>>>();
    k_scatter<<<(SEQ + 255) / 256, 256>>>();
    k_gather<<<SLOTS, 192>>>();
    k_moe_gemm1<<<dim3(NE * 32, (2 * FF) / 128), 256>>>(w_gateup);
    k_silu<<<(SLOTS * FF + 255) / 256, 256>>>();
    k_moe_gemm2<<<dim3(NE * 32, HID / 128), 256>>>(w_down);
    k_combine<<<SEQ, 192>>>(out);
}

// round 5
// speedup vs baseline: 2.5421x; 1.1759x over previous
#include <cuda_runtime.h>
#include <math.h>

// ---------------------------------------------------------------------------
// Constants
// ---------------------------------------------------------------------------
#define SEQ   2048
#define HID   768
#define NQ    12
#define NKV   3
#define HD    64
#define QKVC  1152          // (NQ + 2*NKV) * HD
#define NE    16
#define FF    1536
#define SLOTS 4096          // SEQ * TOPK

// ---------------------------------------------------------------------------
// Device scratch (globals only referenced from device code!)
// ---------------------------------------------------------------------------
__device__ float g_xn1[SEQ * HID];
__device__ float g_qkv[SEQ * QKVC];
__device__ float g_Q[NQ * SEQ * HD];
__device__ float g_K[NKV * SEQ * HD];
__device__ float g_V[NKV * SEQ * HD];
__device__ float g_attn[SEQ * HID];
__device__ float g_h1[SEQ * HID];
__device__ float g_xn2[SEQ * HID];
__device__ int   g_eid[SLOTS];
__device__ float g_ew[SLOTS];
__device__ int   g_cnt[NE];
__device__ int   g_off[NE + 1];
__device__ int   g_cur[NE];
__device__ int   g_ptok[SLOTS];
__device__ int   g_tslot[SLOTS];
__device__ float g_Xp[(size_t)SLOTS * HID];
__device__ float g_Hgu[(size_t)SLOTS * 2 * FF];
__device__ float g_Hact[(size_t)SLOTS * FF];
__device__ float g_Dn[(size_t)SLOTS * HID];

// ---------------------------------------------------------------------------
// TF32 helpers
// ---------------------------------------------------------------------------
__device__ __forceinline__ unsigned f2tf(float f) {
    unsigned u;
    asm("cvt.rna.tf32.f32 %0, %1;" : "=r"(u) : "f"(f));
    return u;
}

__device__ __forceinline__ void mma_tf32(float d[4], const unsigned a[4],
                                         const unsigned b[2]) {
    asm volatile(
        "mma.sync.aligned.m16n8k8.row.col.f32.tf32.tf32.f32 "
        "{%0,%1,%2,%3}, {%4,%5,%6,%7}, {%8,%9}, {%0,%1,%2,%3};"
        : "+f"(d[0]), "+f"(d[1]), "+f"(d[2]), "+f"(d[3])
        : "r"(a[0]), "r"(a[1]), "r"(a[2]), "r"(a[3]),
          "r"(b[0]), "r"(b[1]));
}

__device__ __forceinline__ void cp16(void* smem_dst, const void* gmem_src, bool pred) {
    unsigned d = (unsigned)__cvta_generic_to_shared(smem_dst);
    int sz = pred ? 16 : 0;
    asm volatile("cp.async.cg.shared.global [%0], [%1], 16, %2;"
                 :: "r"(d), "l"(gmem_src), "r"(sz) : "memory");
}

// ---------------------------------------------------------------------------
// RMSNorm
// ---------------------------------------------------------------------------
__device__ __forceinline__ void rmsnorm_row(const float* __restrict__ xr,
                                            const float* __restrict__ w,
                                            float* __restrict__ yr) {
    float s = 0.f;
    for (int i = threadIdx.x; i < HID; i += 256) {
        float v = xr[i];
        s += v * v;
    }
    __shared__ float red[256];
    red[threadIdx.x] = s;
    __syncthreads();
    for (int o = 128; o > 0; o >>= 1) {
        if (threadIdx.x < o) red[threadIdx.x] += red[threadIdx.x + o];
        __syncthreads();
    }
    float scale = rsqrtf(red[0] / (float)HID + 1e-6f);
    for (int i = threadIdx.x; i < HID; i += 256)
        yr[i] = xr[i] * scale * w[i];
}

__global__ void k_rmsnorm1(const float* __restrict__ x, const float* __restrict__ w) {
    int row = blockIdx.x;
    rmsnorm_row(x + (size_t)row * HID, w, g_xn1 + (size_t)row * HID);
}

__global__ void k_rmsnorm2(const float* __restrict__ w) {
    int row = blockIdx.x;
    rmsnorm_row(g_h1 + (size_t)row * HID, w, g_xn2 + (size_t)row * HID);
}

// ---------------------------------------------------------------------------
// TF32 tensor-core GEMM, cp.async double-buffered.
// 128x128 tile, 256 threads (8 warps, 2x4), warp tile 64x32, K-step 16.
// Raw fp32 bits fed to mma.tf32 (HW ignores low mantissa bits -> truncation).
// ---------------------------------------------------------------------------
__device__ __forceinline__ void gemm_tf32_core(const float* __restrict__ A, int lda,
                                               const float* __restrict__ B, int ldb,
                                               int K, int rows, float acc[4][4][4]) {
    __shared__ unsigned sA[2][128][20];   // 80B row stride: 16B-aligned targets
    __shared__ unsigned sB[2][16][132];   // 528B row stride
    int tid  = threadIdx.x;
    int warp = tid >> 5, lane = tid & 31;
    int wm = warp >> 2;                // 0..1
    int wn = warp & 3;                 // 0..3
    int g  = lane >> 2;                // 0..7
    int c  = lane & 3;                 // 0..3

    // staging indices (constant per thread)
    int ar0 = tid >> 2;                 // rows 0..63   (it 0)
    int ar1 = (tid + 256) >> 2;         // rows 64..127 (it 1)
    int akq = (tid & 3) * 4;
    int bkr0 = tid >> 5, bkr1 = (tid + 256) >> 5;
    int bc4 = (tid & 31) * 4;

#define GEMM_STAGE(bufi, k0)                                                      \
    do {                                                                          \
        bool p0 = ar0 < rows, p1 = ar1 < rows;                                    \
        cp16(&sA[bufi][ar0][akq], A + (size_t)(p0 ? ar0 : 0) * lda + (k0) + akq, p0); \
        cp16(&sA[bufi][ar1][akq], A + (size_t)(p1 ? ar1 : 0) * lda + (k0) + akq, p1); \
        cp16(&sB[bufi][bkr0][bc4], B + (size_t)((k0) + bkr0) * ldb + bc4, true);  \
        cp16(&sB[bufi][bkr1][bc4], B + (size_t)((k0) + bkr1) * ldb + bc4, true);  \
        asm volatile("cp.async.commit_group;" ::: "memory");                      \
    } while (0)

    GEMM_STAGE(0, 0);
    int buf = 0;
    for (int k0 = 0; k0 < K; k0 += 16) {
        asm volatile("cp.async.wait_group 0;" ::: "memory");
        __syncthreads();
        if (k0 + 16 < K) GEMM_STAGE(buf ^ 1, k0 + 16);
#pragma unroll
        for (int kk = 0; kk < 16; kk += 8) {
            unsigned af[4][4];
#pragma unroll
            for (int mi = 0; mi < 4; mi++) {
                int m = wm * 64 + mi * 16;
                af[mi][0] = sA[buf][m + g][kk + c];
                af[mi][1] = sA[buf][m + g + 8][kk + c];
                af[mi][2] = sA[buf][m + g][kk + c + 4];
                af[mi][3] = sA[buf][m + g + 8][kk + c + 4];
            }
#pragma unroll
            for (int ni = 0; ni < 4; ni++) {
                int n = wn * 32 + ni * 8 + g;
                unsigned bf[2];
                bf[0] = sB[buf][kk + c][n];
                bf[1] = sB[buf][kk + c + 4][n];
#pragma unroll
                for (int mi = 0; mi < 4; mi++)
                    mma_tf32(acc[mi][ni], af[mi], bf);
            }
        }
        buf ^= 1;
    }
#undef GEMM_STAGE
}

// QKV projection: g_qkv = g_xn1 @ w_qkv   (2048 x 768 x 1152)
__global__ void __launch_bounds__(256) k_gemm_qkv(const float* __restrict__ W) {
    int mb = blockIdx.x, nb = blockIdx.y;
    float acc[4][4][4] = {};
    gemm_tf32_core(g_xn1 + (size_t)mb * 128 * HID, HID, W + nb * 128, QKVC, HID, 128, acc);
    int warp = threadIdx.x >> 5, lane = threadIdx.x & 31;
    int wm = warp >> 2, wn = warp & 3, g = lane >> 2, c = lane & 3;
#pragma unroll
    for (int mi = 0; mi < 4; mi++) {
#pragma unroll
        for (int ni = 0; ni < 4; ni++) {
            int r = mb * 128 + wm * 64 + mi * 16 + g;
            int col = nb * 128 + wn * 32 + ni * 8 + 2 * c;
            *reinterpret_cast<float2*>(g_qkv + (size_t)r * QKVC + col) =
                make_float2(acc[mi][ni][0], acc[mi][ni][1]);
            *reinterpret_cast<float2*>(g_qkv + (size_t)(r + 8) * QKVC + col) =
                make_float2(acc[mi][ni][2], acc[mi][ni][3]);
        }
    }
}

// Out projection + residual: g_h1 = x + g_attn @ w_out   (2048 x 768 x 768)
__global__ void __launch_bounds__(256) k_gemm_out(const float* __restrict__ W,
                                                  const float* __restrict__ xres) {
    int mb = blockIdx.x, nb = blockIdx.y;
    float acc[4][4][4] = {};
    gemm_tf32_core(g_attn + (size_t)mb * 128 * HID, HID, W + nb * 128, HID, HID, 128, acc);
    int warp = threadIdx.x >> 5, lane = threadIdx.x & 31;
    int wm = warp >> 2, wn = warp & 3, g = lane >> 2, c = lane & 3;
#pragma unroll
    for (int mi = 0; mi < 4; mi++) {
#pragma unroll
        for (int ni = 0; ni < 4; ni++) {
            int r = mb * 128 + wm * 64 + mi * 16 + g;
            int col = nb * 128 + wn * 32 + ni * 8 + 2 * c;
            size_t o0 = (size_t)r * HID + col;
            size_t o1 = (size_t)(r + 8) * HID + col;
            float2 x0 = *reinterpret_cast<const float2*>(xres + o0);
            float2 x1 = *reinterpret_cast<const float2*>(xres + o1);
            *reinterpret_cast<float2*>(g_h1 + o0) =
                make_float2(x0.x + acc[mi][ni][0], x0.y + acc[mi][ni][1]);
            *reinterpret_cast<float2*>(g_h1 + o1) =
                make_float2(x1.x + acc[mi][ni][2], x1.y + acc[mi][ni][3]);
        }
    }
}

// MoE GEMM1: Hgu[slot] = Xp[slot] @ w_gate_up[e]   (rows_e x 768 x 3072)
__global__ void __launch_bounds__(256) k_moe_gemm1(const float* __restrict__ Wgu) {
    int e = blockIdx.x >> 4, mb = blockIdx.x & 15, nb = blockIdx.y;
    int r0 = g_off[e];
    int rows_e = g_off[e + 1] - r0;
    int rbase = mb * 128;
    if (rbase >= rows_e) return;
    int rows = min(128, rows_e - rbase);
    float acc[4][4][4] = {};
    gemm_tf32_core(g_Xp + (size_t)(r0 + rbase) * HID, HID,
                   Wgu + (size_t)e * HID * (2 * FF) + nb * 128, 2 * FF, HID, rows, acc);
    int warp = threadIdx.x >> 5, lane = threadIdx.x & 31;
    int wm = warp >> 2, wn = warp & 3, g = lane >> 2, c = lane & 3;
    float* Cp = g_Hgu + (size_t)(r0 + rbase) * (2 * FF) + nb * 128;
#pragma unroll
    for (int mi = 0; mi < 4; mi++) {
#pragma unroll
        for (int ni = 0; ni < 4; ni++) {
            int rr = wm * 64 + mi * 16 + g;
            int col = wn * 32 + ni * 8 + 2 * c;
            if (rr < rows)
                *reinterpret_cast<float2*>(Cp + (size_t)rr * (2 * FF) + col) =
                    make_float2(acc[mi][ni][0], acc[mi][ni][1]);
            if (rr + 8 < rows)
                *reinterpret_cast<float2*>(Cp + (size_t)(rr + 8) * (2 * FF) + col) =
                    make_float2(acc[mi][ni][2], acc[mi][ni][3]);
        }
    }
}

// MoE GEMM2: Dn[slot] = Hact[slot] @ w_down[e]   (rows_e x 1536 x 768)
__global__ void __launch_bounds__(256) k_moe_gemm2(const float* __restrict__ Wd) {
    int e = blockIdx.x >> 4, mb = blockIdx.x & 15, nb = blockIdx.y;
    int r0 = g_off[e];
    int rows_e = g_off[e + 1] - r0;
    int rbase = mb * 128;
    if (rbase >= rows_e) return;
    int rows = min(128, rows_e - rbase);
    float acc[4][4][4] = {};
    gemm_tf32_core(g_Hact + (size_t)(r0 + rbase) * FF, FF,
                   Wd + (size_t)e * FF * HID + nb * 128, HID, FF, rows, acc);
    int warp = threadIdx.x >> 5, lane = threadIdx.x & 31;
    int wm = warp >> 2, wn = warp & 3, g = lane >> 2, c = lane & 3;
    float* Cp = g_Dn + (size_t)(r0 + rbase) * HID + nb * 128;
#pragma unroll
    for (int mi = 0; mi < 4; mi++) {
#pragma unroll
        for (int ni = 0; ni < 4; ni++) {
            int rr = wm * 64 + mi * 16 + g;
            int col = wn * 32 + ni * 8 + 2 * c;
            if (rr < rows)
                *reinterpret_cast<float2*>(Cp + (size_t)rr * HID + col) =
                    make_float2(acc[mi][ni][0], acc[mi][ni][1]);
            if (rr + 8 < rows)
                *reinterpret_cast<float2*>(Cp + (size_t)(rr + 8) * HID + col) =
                    make_float2(acc[mi][ni][2], acc[mi][ni][3]);
        }
    }
}

// ---------------------------------------------------------------------------
// RoPE + split into head-major Q/K/V
// ---------------------------------------------------------------------------
__global__ void k_rope(void) {
    int s = blockIdx.x;
    int p = threadIdx.x;
    const float* row = g_qkv + (size_t)s * QKVC;
    if (p < 384) {
        int h = p >> 5, i = p & 31;
        float v0 = row[h * HD + 2 * i];
        float v1 = row[h * HD + 2 * i + 1];
        float inv = powf(10000.f, -(float)(2 * i) / (float)HD);
        float ang = (float)s * inv;
        float sn, cs;
        sincosf(ang, &sn, &cs);
        float* dst = g_Q + ((size_t)h * SEQ + s) * HD;
        dst[2 * i]     = v0 * cs - v1 * sn;
        dst[2 * i + 1] = v0 * sn + v1 * cs;
    } else if (p < 480) {
        int q = p - 384;
        int h = q >> 5, i = q & 31;
        float v0 = row[NQ * HD + h * HD + 2 * i];
        float v1 = row[NQ * HD + h * HD + 2 * i + 1];
        float inv = powf(10000.f, -(float)(2 * i) / (float)HD);
        float ang = (float)s * inv;
        float sn, cs;
        sincosf(ang, &sn, &cs);
        float* dst = g_K + ((size_t)h * SEQ + s) * HD;
        dst[2 * i]     = v0 * cs - v1 * sn;
        dst[2 * i + 1] = v0 * sn + v1 * cs;
    } else {
        int q = p - 480;
        int h = q >> 5, i = q & 31;
        float* dst = g_V + ((size_t)h * SEQ + s) * HD;
        dst[2 * i]     = row[(NQ + NKV) * HD + h * HD + 2 * i];
        dst[2 * i + 1] = row[(NQ + NKV) * HD + h * HD + 2 * i + 1];
    }
}

// ---------------------------------------------------------------------------
// Flash attention, TF32 tensor cores. Block = (64-query tile, head).
// 256 threads = 8 warps (2x4). Warp tiles 32x16 for both S=QK^T and O=PV.
// ---------------------------------------------------------------------------
#define ATT_SMEM_BYTES ((4 * 64 * 68 + 64 * 65 + 3 * 64) * 4)

__global__ void k_attn(void) {
    extern __shared__ unsigned smu[];
    unsigned* uQ = smu;               // [64][68] tf32
    unsigned* uK = uQ + 64 * 68;      // [64][68] tf32
    unsigned* uV = uK + 64 * 68;      // [64][68] tf32
    unsigned* uP = uV + 64 * 68;      // [64][68] tf32
    float* Sm    = (float*)(uP + 64 * 68);  // [64][65]
    float* mrow  = Sm + 64 * 65;
    float* lrow  = mrow + 64;
    float* arow  = lrow + 64;

    int qb = gridDim.x - 1 - blockIdx.x;   // heavy tiles first (load balance)
    int h  = blockIdx.y;
    int kvh = h >> 2;                      // REP = 4
    int tid = threadIdx.x;
    int warp = tid >> 5, lane = tid & 31;
    int wm = warp >> 2, wn = warp & 3;     // 2 x 4 warp grid
    int g  = lane >> 2, c = lane & 3;

    const float* Qb = g_Q + ((size_t)h * SEQ + qb * 64) * HD;
    for (int e = tid; e < 4096; e += 256) {
        int r = e >> 6, d = e & 63;
        uQ[r * 68 + d] = f2tf(Qb[r * HD + d] * 0.125f);  // 1/sqrt(64)
    }
    if (tid < 64) { mrow[tid] = -1e30f; lrow[tid] = 0.f; }

    float oacc[2][2][4] = {};
    for (int kb = 0; kb <= qb; kb++) {
        const float* Kb = g_K + ((size_t)kvh * SEQ + kb * 64) * HD;
        const float* Vb = g_V + ((size_t)kvh * SEQ + kb * 64) * HD;
        __syncthreads();                   // uK/uV free (prev PV done)
        for (int e = tid; e < 4096; e += 256) {
            int r = e >> 6, d = e & 63;
            uK[r * 68 + d] = f2tf(Kb[r * HD + d]);
            uV[r * 68 + d] = f2tf(Vb[r * HD + d]);
        }
        __syncthreads();

        // ---- S = Q @ K^T (64x64), warp tile 32x16 ----
        float sacc[2][2][4] = {};
#pragma unroll
        for (int kk = 0; kk < 64; kk += 8) {
            unsigned af[2][4];
#pragma unroll
            for (int mi = 0; mi < 2; mi++) {
                int m = wm * 32 + mi * 16;
                af[mi][0] = uQ[(m + g) * 68 + kk + c];
                af[mi][1] = uQ[(m + g + 8) * 68 + kk + c];
                af[mi][2] = uQ[(m + g) * 68 + kk + c + 4];
                af[mi][3] = uQ[(m + g + 8) * 68 + kk + c + 4];
            }
#pragma unroll
            for (int ni = 0; ni < 2; ni++) {
                int n = wn * 16 + ni * 8 + g;
                unsigned bf[2];
                bf[0] = uK[n * 68 + kk + c];
                bf[1] = uK[n * 68 + kk + c + 4];
#pragma unroll
                for (int mi = 0; mi < 2; mi++)
                    mma_tf32(sacc[mi][ni], af[mi], bf);
            }
        }
        // write masked S to smem
        bool diag = (kb == qb);
#pragma unroll
        for (int mi = 0; mi < 2; mi++) {
#pragma unroll
            for (int ni = 0; ni < 2; ni++) {
                int r0 = wm * 32 + mi * 16 + g;
                int cl = wn * 16 + ni * 8 + 2 * c;
                float v0 = sacc[mi][ni][0], v1 = sacc[mi][ni][1];
                float v2 = sacc[mi][ni][2], v3 = sacc[mi][ni][3];
                if (diag) {
                    if (cl > r0)     v0 = -1e30f;
                    if (cl + 1 > r0) v1 = -1e30f;
                    if (cl > r0 + 8)     v2 = -1e30f;
                    if (cl + 1 > r0 + 8) v3 = -1e30f;
                }
                Sm[r0 * 65 + cl]           = v0;
                Sm[r0 * 65 + cl + 1]       = v1;
                Sm[(r0 + 8) * 65 + cl]     = v2;
                Sm[(r0 + 8) * 65 + cl + 1] = v3;
            }
        }
        __syncthreads();

        // ---- online softmax: 4 lanes per row, write P (tf32) row-major ----
        {
            int i  = tid >> 2;
            int jq = (tid & 3) * 16;
            float mx = -1e30f;
#pragma unroll
            for (int j = 0; j < 16; j++) mx = fmaxf(mx, Sm[i * 65 + jq + j]);
            mx = fmaxf(mx, __shfl_xor_sync(0xffffffffu, mx, 1));
            mx = fmaxf(mx, __shfl_xor_sync(0xffffffffu, mx, 2));
            float mold = mrow[i];
            mx = fmaxf(mx, mold);
            float sum = 0.f;
#pragma unroll
            for (int j = 0; j < 16; j++) {
                float p = __expf(Sm[i * 65 + jq + j] - mx);
                uP[i * 68 + jq + j] = f2tf(p);
                sum += p;
            }
            sum += __shfl_xor_sync(0xffffffffu, sum, 1);
            sum += __shfl_xor_sync(0xffffffffu, sum, 2);
            if ((tid & 3) == 0) {
                float al = __expf(mold - mx);
                lrow[i] = lrow[i] * al + sum;
                mrow[i] = mx;
                arow[i] = al;
            }
        }
        __syncthreads();

        // ---- rescale O accumulators by alpha ----
#pragma unroll
        for (int mi = 0; mi < 2; mi++) {
            float a0 = arow[wm * 32 + mi * 16 + g];
            float a1 = arow[wm * 32 + mi * 16 + g + 8];
#pragma unroll
            for (int ni = 0; ni < 2; ni++) {
                oacc[mi][ni][0] *= a0;
                oacc[mi][ni][1] *= a0;
                oacc[mi][ni][2] *= a1;
                oacc[mi][ni][3] *= a1;
            }
        }

        // ---- O += P @ V (64x64) ----
#pragma unroll
        for (int kk = 0; kk < 64; kk += 8) {
            unsigned af[2][4];
#pragma unroll
            for (int mi = 0; mi < 2; mi++) {
                int m = wm * 32 + mi * 16;
                af[mi][0] = uP[(m + g) * 68 + kk + c];
                af[mi][1] = uP[(m + g + 8) * 68 + kk + c];
                af[mi][2] = uP[(m + g) * 68 + kk + c + 4];
                af[mi][3] = uP[(m + g + 8) * 68 + kk + c + 4];
            }
#pragma unroll
            for (int ni = 0; ni < 2; ni++) {
                int n = wn * 16 + ni * 8 + g;
                unsigned bf[2];
                bf[0] = uV[(kk + c) * 68 + n];
                bf[1] = uV[(kk + c + 4) * 68 + n];
#pragma unroll
                for (int mi = 0; mi < 2; mi++)
                    mma_tf32(oacc[mi][ni], af[mi], bf);
            }
        }
    }

    // ---- epilogue: O / l, write head-interleaved ----
    __syncthreads();
#pragma unroll
    for (int mi = 0; mi < 2; mi++) {
        int rl0 = wm * 32 + mi * 16 + g;
        float i0 = 1.f / lrow[rl0];
        float i1 = 1.f / lrow[rl0 + 8];
        int gr0 = qb * 64 + rl0;
#pragma unroll
        for (int ni = 0; ni < 2; ni++) {
            int col = h * HD + wn * 16 + ni * 8 + 2 * c;
            *reinterpret_cast<float2*>(g_attn + (size_t)gr0 * HID + col) =
                make_float2(oacc[mi][ni][0] * i0, oacc[mi][ni][1] * i0);
            *reinterpret_cast<float2*>(g_attn + (size_t)(gr0 + 8) * HID + col) =
                make_float2(oacc[mi][ni][2] * i1, oacc[mi][ni][3] * i1);
        }
    }
}

// ---------------------------------------------------------------------------
// MoE routing / permutation (fp32 router — expert picks must not flip)
// ---------------------------------------------------------------------------
__global__ void k_reset(void) {
    if (threadIdx.x < NE) {
        g_cnt[threadIdx.x] = 0;
        g_cur[threadIdx.x] = 0;
    }
}

__global__ void k_router(const float* __restrict__ Wr) {
    int t = blockIdx.x;
    int w = threadIdx.x >> 5, lane = threadIdx.x & 31;
    __shared__ float lg[NE];
    const float* xr = g_xn2 + (size_t)t * HID;
    float s = 0.f;
    for (int k = lane; k < HID; k += 32) s += xr[k] * Wr[k * NE + w];
#pragma unroll
    for (int o = 16; o > 0; o >>= 1) s += __shfl_xor_sync(0xffffffffu, s, o);
    if (lane == 0) lg[w] = s;
    __syncthreads();
    if (threadIdx.x == 0) {
        int b0 = 0;
        float v0 = lg[0];
        for (int e = 1; e < NE; e++)
            if (lg[e] > v0) { v0 = lg[e]; b0 = e; }
        int b1 = -1;
        float v1 = -3e38f;
        for (int e = 0; e < NE; e++)
            if (e != b0 && lg[e] > v1) { v1 = lg[e]; b1 = e; }
        float w0 = 1.f / (1.f + __expf(v1 - v0));
        g_eid[2 * t] = b0;
        g_eid[2 * t + 1] = b1;
        g_ew[2 * t] = w0;
        g_ew[2 * t + 1] = 1.f - w0;
        atomicAdd(&g_cnt[b0], 1);
        atomicAdd(&g_cnt[b1], 1);
    }
}

__global__ void k_scan(void) {
    if (threadIdx.x == 0) {
        int a = 0;
        for (int e = 0; e < NE; e++) {
            g_off[e] = a;
            a += g_cnt[e];
        }
        g_off[NE] = a;
    }
}

__global__ void k_scatter(void) {
    int t = blockIdx.x * blockDim.x + threadIdx.x;
    if (t >= SEQ) return;
#pragma unroll
    for (int slot = 0; slot < 2; slot++) {
        int e = g_eid[2 * t + slot];
        int pos = g_off[e] + atomicAdd(&g_cur[e], 1);
        g_ptok[pos] = t;
        g_tslot[2 * t + slot] = pos;
    }
}

__global__ void k_gather(void) {
    int pos = blockIdx.x;
    int tok = g_ptok[pos];
    const float4* src = reinterpret_cast<const float4*>(g_xn2 + (size_t)tok * HID);
    float4* dst = reinterpret_cast<float4*>(g_Xp + (size_t)pos * HID);
    dst[threadIdx.x] = src[threadIdx.x];
}

__global__ void k_silu(void) {
    int idx = blockIdx.x * blockDim.x + threadIdx.x;
    const int total = SLOTS * FF;
    if (idx >= total) return;
    int pos = idx / FF, j = idx - pos * FF;
    float g = g_Hgu[(size_t)pos * (2 * FF) + j];
    float u = g_Hgu[(size_t)pos * (2 * FF) + FF + j];
    float sg = g / (1.f + __expf(-g));
    g_Hact[idx] = sg * u;
}

__global__ void k_combine(float* __restrict__ out) {
    int t = blockIdx.x;
    int i = threadIdx.x;
    int p0 = g_tslot[2 * t], p1 = g_tslot[2 * t + 1];
    float w0 = g_ew[2 * t], w1 = g_ew[2 * t + 1];
    float4 a = reinterpret_cast<const float4*>(g_h1 + (size_t)t * HID)[i];
    float4 b = reinterpret_cast<const float4*>(g_Dn + (size_t)p0 * HID)[i];
    float4 c = reinterpret_cast<const float4*>(g_Dn + (size_t)p1 * HID)[i];
    float4 o = make_float4(a.x + w0 * b.x + w1 * c.x,
                           a.y + w0 * b.y + w1 * c.y,
                           a.z + w0 * b.z + w1 * c.z,
                           a.w + w0 * b.w + w1 * c.w);
    reinterpret_cast<float4*>(out + (size_t)t * HID)[i] = o;
}

// ---------------------------------------------------------------------------
// Launch
// ---------------------------------------------------------------------------
extern "C" void kernel_launch(void* const* d_in, const int* in_sizes, int n_in,
                              void* d_out, int out_size) {
    (void)in_sizes; (void)n_in; (void)out_size;
    const float* x        = (const float*)d_in[0];
    const float* norm1_w  = (const float*)d_in[1];
    const float* w_qkv    = (const float*)d_in[2];
    const float* w_out    = (const float*)d_in[3];
    const float* norm2_w  = (const float*)d_in[4];
    const float* w_router = (const float*)d_in[5];
    const float* w_gateup = (const float*)d_in[6];
    const float* w_down   = (const float*)d_in[7];
    float* out = (float*)d_out;

    cudaFuncSetAttribute(k_attn, cudaFuncAttributeMaxDynamicSharedMemorySize,
                         ATT_SMEM_BYTES);

    k_reset<<<1, 32>>>();
    k_rmsnorm1<<<SEQ, 256>>>(x, norm1_w);
    k_gemm_qkv<<<dim3(SEQ / 128, QKVC / 128), 256>>>(w_qkv);
    k_rope<<<SEQ, 576>>>();
    k_attn<<<dim3(SEQ / 64, NQ), 256, ATT_SMEM_BYTES>>>();
    k_gemm_out<<<dim3(SEQ / 128, HID / 128), 256>>>(w_out, x);
    k_rmsnorm2<<<SEQ, 256>>>(norm2_w);
    k_router<<<SEQ, 512>>>(w_router);
    k_scan<<<1, 32>>>();
    k_scatter<<<(SEQ + 255) / 256, 256>>>();
    k_gather<<<SLOTS, 192>>>();
    k_moe_gemm1<<<dim3(NE * 16, (2 * FF) / 128), 256>>>(w_gateup);
    k_silu<<<(SLOTS * FF + 255) / 256, 256>>>();
    k_moe_gemm2<<<dim3(NE * 16, HID / 128), 256>>>(w_down);
    k_combine<<<SEQ, 192>>>(out);
}

// round 6
// speedup vs baseline: 2.5531x; 1.0043x over previous
#include <cuda_runtime.h>
#include <math.h>

// ---------------------------------------------------------------------------
// Constants
// ---------------------------------------------------------------------------
#define SEQ   2048
#define HID   768
#define NQ    12
#define NKV   3
#define HD    64
#define QKVC  1152          // (NQ + 2*NKV) * HD
#define NE    16
#define FF    1536
#define SLOTS 4096          // SEQ * TOPK

// ---------------------------------------------------------------------------
// Device scratch (globals only referenced from device code!)
// ---------------------------------------------------------------------------
__device__ float g_xn1[SEQ * HID];
__device__ float g_qkv[SEQ * QKVC];
__device__ float g_Q[NQ * SEQ * HD];
__device__ float g_K[NKV * SEQ * HD];
__device__ float g_V[NKV * SEQ * HD];
__device__ float g_attn[SEQ * HID];
__device__ float g_h1[SEQ * HID];
__device__ float g_xn2[SEQ * HID];
__device__ int   g_eid[SLOTS];
__device__ float g_ew[SLOTS];
__device__ int   g_cnt[NE];
__device__ int   g_off[NE + 1];
__device__ int   g_cur[NE];
__device__ int   g_ptok[SLOTS];
__device__ int   g_tslot[SLOTS];
__device__ float g_Xp[(size_t)SLOTS * HID];
__device__ float g_Hgu[(size_t)SLOTS * 2 * FF];
__device__ float g_Hact[(size_t)SLOTS * FF];
__device__ float g_Dn[(size_t)SLOTS * HID];

// ---------------------------------------------------------------------------
// TF32 helpers
// ---------------------------------------------------------------------------
__device__ __forceinline__ unsigned f2tf(float f) {
    unsigned u;
    asm("cvt.rna.tf32.f32 %0, %1;" : "=r"(u) : "f"(f));
    return u;
}

__device__ __forceinline__ void mma_tf32(float d[4], const unsigned a[4],
                                         const unsigned b[2]) {
    asm volatile(
        "mma.sync.aligned.m16n8k8.row.col.f32.tf32.tf32.f32 "
        "{%0,%1,%2,%3}, {%4,%5,%6,%7}, {%8,%9}, {%0,%1,%2,%3};"
        : "+f"(d[0]), "+f"(d[1]), "+f"(d[2]), "+f"(d[3])
        : "r"(a[0]), "r"(a[1]), "r"(a[2]), "r"(a[3]),
          "r"(b[0]), "r"(b[1]));
}

__device__ __forceinline__ void cp16(void* smem_dst, const void* gmem_src, bool pred) {
    unsigned d = (unsigned)__cvta_generic_to_shared(smem_dst);
    int sz = pred ? 16 : 0;
    asm volatile("cp.async.cg.shared.global [%0], [%1], 16, %2;"
                 :: "r"(d), "l"(gmem_src), "r"(sz) : "memory");
}

// ---------------------------------------------------------------------------
// RMSNorm
// ---------------------------------------------------------------------------
__device__ __forceinline__ void rmsnorm_row(const float* __restrict__ xr,
                                            const float* __restrict__ w,
                                            float* __restrict__ yr) {
    float s = 0.f;
    for (int i = threadIdx.x; i < HID; i += 256) {
        float v = xr[i];
        s += v * v;
    }
    __shared__ float red[256];
    red[threadIdx.x] = s;
    __syncthreads();
    for (int o = 128; o > 0; o >>= 1) {
        if (threadIdx.x < o) red[threadIdx.x] += red[threadIdx.x + o];
        __syncthreads();
    }
    float scale = rsqrtf(red[0] / (float)HID + 1e-6f);
    for (int i = threadIdx.x; i < HID; i += 256)
        yr[i] = xr[i] * scale * w[i];
}

__global__ void k_rmsnorm1(const float* __restrict__ x, const float* __restrict__ w) {
    int row = blockIdx.x;
    rmsnorm_row(x + (size_t)row * HID, w, g_xn1 + (size_t)row * HID);
}

__global__ void k_rmsnorm2(const float* __restrict__ w) {
    int row = blockIdx.x;
    rmsnorm_row(g_h1 + (size_t)row * HID, w, g_xn2 + (size_t)row * HID);
}

// ---------------------------------------------------------------------------
// TF32 tensor-core GEMM, cp.async double-buffered.
// 128x128 tile, 256 threads (8 warps, 2x4), warp tile 64x32, K-step 16.
// Raw fp32 bits fed to mma.tf32 (HW ignores low mantissa bits -> truncation).
// ---------------------------------------------------------------------------
__device__ __forceinline__ void gemm_tf32_core(const float* __restrict__ A, int lda,
                                               const float* __restrict__ B, int ldb,
                                               int K, int rows, float acc[4][4][4]) {
    __shared__ unsigned sA[2][128][20];   // 80B row stride: 16B-aligned targets
    __shared__ unsigned sB[2][16][132];   // 528B row stride
    int tid  = threadIdx.x;
    int warp = tid >> 5, lane = tid & 31;
    int wm = warp >> 2;                // 0..1
    int wn = warp & 3;                 // 0..3
    int g  = lane >> 2;                // 0..7
    int c  = lane & 3;                 // 0..3

    // staging indices (constant per thread)
    int ar0 = tid >> 2;                 // rows 0..63   (it 0)
    int ar1 = (tid + 256) >> 2;         // rows 64..127 (it 1)
    int akq = (tid & 3) * 4;
    int bkr0 = tid >> 5, bkr1 = (tid + 256) >> 5;
    int bc4 = (tid & 31) * 4;

#define GEMM_STAGE(bufi, k0)                                                      \
    do {                                                                          \
        bool p0 = ar0 < rows, p1 = ar1 < rows;                                    \
        cp16(&sA[bufi][ar0][akq], A + (size_t)(p0 ? ar0 : 0) * lda + (k0) + akq, p0); \
        cp16(&sA[bufi][ar1][akq], A + (size_t)(p1 ? ar1 : 0) * lda + (k0) + akq, p1); \
        cp16(&sB[bufi][bkr0][bc4], B + (size_t)((k0) + bkr0) * ldb + bc4, true);  \
        cp16(&sB[bufi][bkr1][bc4], B + (size_t)((k0) + bkr1) * ldb + bc4, true);  \
        asm volatile("cp.async.commit_group;" ::: "memory");                      \
    } while (0)

    GEMM_STAGE(0, 0);
    int buf = 0;
    for (int k0 = 0; k0 < K; k0 += 16) {
        asm volatile("cp.async.wait_group 0;" ::: "memory");
        __syncthreads();
        if (k0 + 16 < K) GEMM_STAGE(buf ^ 1, k0 + 16);
#pragma unroll
        for (int kk = 0; kk < 16; kk += 8) {
            unsigned af[4][4];
#pragma unroll
            for (int mi = 0; mi < 4; mi++) {
                int m = wm * 64 + mi * 16;
                af[mi][0] = sA[buf][m + g][kk + c];
                af[mi][1] = sA[buf][m + g + 8][kk + c];
                af[mi][2] = sA[buf][m + g][kk + c + 4];
                af[mi][3] = sA[buf][m + g + 8][kk + c + 4];
            }
#pragma unroll
            for (int ni = 0; ni < 4; ni++) {
                int n = wn * 32 + ni * 8 + g;
                unsigned bf[2];
                bf[0] = sB[buf][kk + c][n];
                bf[1] = sB[buf][kk + c + 4][n];
#pragma unroll
                for (int mi = 0; mi < 4; mi++)
                    mma_tf32(acc[mi][ni], af[mi], bf);
            }
        }
        buf ^= 1;
    }
#undef GEMM_STAGE
}

// QKV projection: g_qkv = g_xn1 @ w_qkv   (2048 x 768 x 1152)
__global__ void __launch_bounds__(256) k_gemm_qkv(const float* __restrict__ W) {
    int mb = blockIdx.x, nb = blockIdx.y;
    float acc[4][4][4] = {};
    gemm_tf32_core(g_xn1 + (size_t)mb * 128 * HID, HID, W + nb * 128, QKVC, HID, 128, acc);
    int warp = threadIdx.x >> 5, lane = threadIdx.x & 31;
    int wm = warp >> 2, wn = warp & 3, g = lane >> 2, c = lane & 3;
#pragma unroll
    for (int mi = 0; mi < 4; mi++) {
#pragma unroll
        for (int ni = 0; ni < 4; ni++) {
            int r = mb * 128 + wm * 64 + mi * 16 + g;
            int col = nb * 128 + wn * 32 + ni * 8 + 2 * c;
            *reinterpret_cast<float2*>(g_qkv + (size_t)r * QKVC + col) =
                make_float2(acc[mi][ni][0], acc[mi][ni][1]);
            *reinterpret_cast<float2*>(g_qkv + (size_t)(r + 8) * QKVC + col) =
                make_float2(acc[mi][ni][2], acc[mi][ni][3]);
        }
    }
}

// Out projection + residual: g_h1 = x + g_attn @ w_out   (2048 x 768 x 768)
__global__ void __launch_bounds__(256) k_gemm_out(const float* __restrict__ W,
                                                  const float* __restrict__ xres) {
    int mb = blockIdx.x, nb = blockIdx.y;
    float acc[4][4][4] = {};
    gemm_tf32_core(g_attn + (size_t)mb * 128 * HID, HID, W + nb * 128, HID, HID, 128, acc);
    int warp = threadIdx.x >> 5, lane = threadIdx.x & 31;
    int wm = warp >> 2, wn = warp & 3, g = lane >> 2, c = lane & 3;
#pragma unroll
    for (int mi = 0; mi < 4; mi++) {
#pragma unroll
        for (int ni = 0; ni < 4; ni++) {
            int r = mb * 128 + wm * 64 + mi * 16 + g;
            int col = nb * 128 + wn * 32 + ni * 8 + 2 * c;
            size_t o0 = (size_t)r * HID + col;
            size_t o1 = (size_t)(r + 8) * HID + col;
            float2 x0 = *reinterpret_cast<const float2*>(xres + o0);
            float2 x1 = *reinterpret_cast<const float2*>(xres + o1);
            *reinterpret_cast<float2*>(g_h1 + o0) =
                make_float2(x0.x + acc[mi][ni][0], x0.y + acc[mi][ni][1]);
            *reinterpret_cast<float2*>(g_h1 + o1) =
                make_float2(x1.x + acc[mi][ni][2], x1.y + acc[mi][ni][3]);
        }
    }
}

// MoE GEMM1: Hgu[slot] = Xp[slot] @ w_gate_up[e]   (rows_e x 768 x 3072)
__global__ void __launch_bounds__(256) k_moe_gemm1(const float* __restrict__ Wgu) {
    int e = blockIdx.x >> 4, mb = blockIdx.x & 15, nb = blockIdx.y;
    int r0 = g_off[e];
    int rows_e = g_off[e + 1] - r0;
    int rbase = mb * 128;
    if (rbase >= rows_e) return;
    int rows = min(128, rows_e - rbase);
    float acc[4][4][4] = {};
    gemm_tf32_core(g_Xp + (size_t)(r0 + rbase) * HID, HID,
                   Wgu + (size_t)e * HID * (2 * FF) + nb * 128, 2 * FF, HID, rows, acc);
    int warp = threadIdx.x >> 5, lane = threadIdx.x & 31;
    int wm = warp >> 2, wn = warp & 3, g = lane >> 2, c = lane & 3;
    float* Cp = g_Hgu + (size_t)(r0 + rbase) * (2 * FF) + nb * 128;
#pragma unroll
    for (int mi = 0; mi < 4; mi++) {
#pragma unroll
        for (int ni = 0; ni < 4; ni++) {
            int rr = wm * 64 + mi * 16 + g;
            int col = wn * 32 + ni * 8 + 2 * c;
            if (rr < rows)
                *reinterpret_cast<float2*>(Cp + (size_t)rr * (2 * FF) + col) =
                    make_float2(acc[mi][ni][0], acc[mi][ni][1]);
            if (rr + 8 < rows)
                *reinterpret_cast<float2*>(Cp + (size_t)(rr + 8) * (2 * FF) + col) =
                    make_float2(acc[mi][ni][2], acc[mi][ni][3]);
        }
    }
}

// MoE GEMM2: Dn[slot] = Hact[slot] @ w_down[e]   (rows_e x 1536 x 768)
__global__ void __launch_bounds__(256) k_moe_gemm2(const float* __restrict__ Wd) {
    int e = blockIdx.x >> 4, mb = blockIdx.x & 15, nb = blockIdx.y;
    int r0 = g_off[e];
    int rows_e = g_off[e + 1] - r0;
    int rbase = mb * 128;
    if (rbase >= rows_e) return;
    int rows = min(128, rows_e - rbase);
    float acc[4][4][4] = {};
    gemm_tf32_core(g_Hact + (size_t)(r0 + rbase) * FF, FF,
                   Wd + (size_t)e * FF * HID + nb * 128, HID, FF, rows, acc);
    int warp = threadIdx.x >> 5, lane = threadIdx.x & 31;
    int wm = warp >> 2, wn = warp & 3, g = lane >> 2, c = lane & 3;
    float* Cp = g_Dn + (size_t)(r0 + rbase) * HID + nb * 128;
#pragma unroll
    for (int mi = 0; mi < 4; mi++) {
#pragma unroll
        for (int ni = 0; ni < 4; ni++) {
            int rr = wm * 64 + mi * 16 + g;
            int col = wn * 32 + ni * 8 + 2 * c;
            if (rr < rows)
                *reinterpret_cast<float2*>(Cp + (size_t)rr * HID + col) =
                    make_float2(acc[mi][ni][0], acc[mi][ni][1]);
            if (rr + 8 < rows)
                *reinterpret_cast<float2*>(Cp + (size_t)(rr + 8) * HID + col) =
                    make_float2(acc[mi][ni][2], acc[mi][ni][3]);
        }
    }
}

// ---------------------------------------------------------------------------
// RoPE + split into head-major Q/K/V
// ---------------------------------------------------------------------------
__global__ void k_rope(void) {
    int s = blockIdx.x;
    int p = threadIdx.x;
    const float* row = g_qkv + (size_t)s * QKVC;
    if (p < 384) {
        int h = p >> 5, i = p & 31;
        float v0 = row[h * HD + 2 * i];
        float v1 = row[h * HD + 2 * i + 1];
        float inv = powf(10000.f, -(float)(2 * i) / (float)HD);
        float ang = (float)s * inv;
        float sn, cs;
        sincosf(ang, &sn, &cs);
        float* dst = g_Q + ((size_t)h * SEQ + s) * HD;
        dst[2 * i]     = v0 * cs - v1 * sn;
        dst[2 * i + 1] = v0 * sn + v1 * cs;
    } else if (p < 480) {
        int q = p - 384;
        int h = q >> 5, i = q & 31;
        float v0 = row[NQ * HD + h * HD + 2 * i];
        float v1 = row[NQ * HD + h * HD + 2 * i + 1];
        float inv = powf(10000.f, -(float)(2 * i) / (float)HD);
        float ang = (float)s * inv;
        float sn, cs;
        sincosf(ang, &sn, &cs);
        float* dst = g_K + ((size_t)h * SEQ + s) * HD;
        dst[2 * i]     = v0 * cs - v1 * sn;
        dst[2 * i + 1] = v0 * sn + v1 * cs;
    } else {
        int q = p - 480;
        int h = q >> 5, i = q & 31;
        float* dst = g_V + ((size_t)h * SEQ + s) * HD;
        dst[2 * i]     = row[(NQ + NKV) * HD + h * HD + 2 * i];
        dst[2 * i + 1] = row[(NQ + NKV) * HD + h * HD + 2 * i + 1];
    }
}

// ---------------------------------------------------------------------------
// Flash attention, TF32 tensor cores. Block = (64-query tile, head).
// 256 threads = 8 warps (2x4). Warp tiles 32x16 for both S=QK^T and O=PV.
// ---------------------------------------------------------------------------
#define ATT_SMEM_BYTES ((4 * 64 * 68 + 64 * 65 + 3 * 64) * 4)

__global__ void k_attn(void) {
    extern __shared__ unsigned smu[];
    unsigned* uQ = smu;               // [64][68] tf32
    unsigned* uK = uQ + 64 * 68;      // [64][68] tf32
    unsigned* uV = uK + 64 * 68;      // [64][68] tf32
    unsigned* uP = uV + 64 * 68;      // [64][68] tf32
    float* Sm    = (float*)(uP + 64 * 68);  // [64][65]
    float* mrow  = Sm + 64 * 65;
    float* lrow  = mrow + 64;
    float* arow  = lrow + 64;

    int qb = gridDim.x - 1 - blockIdx.x;   // heavy tiles first (load balance)
    int h  = blockIdx.y;
    int kvh = h >> 2;                      // REP = 4
    int tid = threadIdx.x;
    int warp = tid >> 5, lane = tid & 31;
    int wm = warp >> 2, wn = warp & 3;     // 2 x 4 warp grid
    int g  = lane >> 2, c = lane & 3;

    const float* Qb = g_Q + ((size_t)h * SEQ + qb * 64) * HD;
    for (int e = tid; e < 4096; e += 256) {
        int r = e >> 6, d = e & 63;
        uQ[r * 68 + d] = f2tf(Qb[r * HD + d] * 0.125f);  // 1/sqrt(64)
    }
    if (tid < 64) { mrow[tid] = -1e30f; lrow[tid] = 0.f; }

    float oacc[2][2][4] = {};
    for (int kb = 0; kb <= qb; kb++) {
        const float* Kb = g_K + ((size_t)kvh * SEQ + kb * 64) * HD;
        const float* Vb = g_V + ((size_t)kvh * SEQ + kb * 64) * HD;
        __syncthreads();                   // uK/uV free (prev PV done)
        for (int e = tid; e < 4096; e += 256) {
            int r = e >> 6, d = e & 63;
            uK[r * 68 + d] = f2tf(Kb[r * HD + d]);
            uV[r * 68 + d] = f2tf(Vb[r * HD + d]);
        }
        __syncthreads();

        // ---- S = Q @ K^T (64x64), warp tile 32x16 ----
        float sacc[2][2][4] = {};
#pragma unroll
        for (int kk = 0; kk < 64; kk += 8) {
            unsigned af[2][4];
#pragma unroll
            for (int mi = 0; mi < 2; mi++) {
                int m = wm * 32 + mi * 16;
                af[mi][0] = uQ[(m + g) * 68 + kk + c];
                af[mi][1] = uQ[(m + g + 8) * 68 + kk + c];
                af[mi][2] = uQ[(m + g) * 68 + kk + c + 4];
                af[mi][3] = uQ[(m + g + 8) * 68 + kk + c + 4];
            }
#pragma unroll
            for (int ni = 0; ni < 2; ni++) {
                int n = wn * 16 + ni * 8 + g;
                unsigned bf[2];
                bf[0] = uK[n * 68 + kk + c];
                bf[1] = uK[n * 68 + kk + c + 4];
#pragma unroll
                for (int mi = 0; mi < 2; mi++)
                    mma_tf32(sacc[mi][ni], af[mi], bf);
            }
        }
        // write masked S to smem
        bool diag = (kb == qb);
#pragma unroll
        for (int mi = 0; mi < 2; mi++) {
#pragma unroll
            for (int ni = 0; ni < 2; ni++) {
                int r0 = wm * 32 + mi * 16 + g;
                int cl = wn * 16 + ni * 8 + 2 * c;
                float v0 = sacc[mi][ni][0], v1 = sacc[mi][ni][1];
                float v2 = sacc[mi][ni][2], v3 = sacc[mi][ni][3];
                if (diag) {
                    if (cl > r0)     v0 = -1e30f;
                    if (cl + 1 > r0) v1 = -1e30f;
                    if (cl > r0 + 8)     v2 = -1e30f;
                    if (cl + 1 > r0 + 8) v3 = -1e30f;
                }
                Sm[r0 * 65 + cl]           = v0;
                Sm[r0 * 65 + cl + 1]       = v1;
                Sm[(r0 + 8) * 65 + cl]     = v2;
                Sm[(r0 + 8) * 65 + cl + 1] = v3;
            }
        }
        __syncthreads();

        // ---- online softmax: 4 lanes per row, write P (tf32) row-major ----
        {
            int i  = tid >> 2;
            int jq = (tid & 3) * 16;
            float mx = -1e30f;
#pragma unroll
            for (int j = 0; j < 16; j++) mx = fmaxf(mx, Sm[i * 65 + jq + j]);
            mx = fmaxf(mx, __shfl_xor_sync(0xffffffffu, mx, 1));
            mx = fmaxf(mx, __shfl_xor_sync(0xffffffffu, mx, 2));
            float mold = mrow[i];
            mx = fmaxf(mx, mold);
            float sum = 0.f;
#pragma unroll
            for (int j = 0; j < 16; j++) {
                float p = __expf(Sm[i * 65 + jq + j] - mx);
                uP[i * 68 + jq + j] = f2tf(p);
                sum += p;
            }
            sum += __shfl_xor_sync(0xffffffffu, sum, 1);
            sum += __shfl_xor_sync(0xffffffffu, sum, 2);
            if ((tid & 3) == 0) {
                float al = __expf(mold - mx);
                lrow[i] = lrow[i] * al + sum;
                mrow[i] = mx;
                arow[i] = al;
            }
        }
        __syncthreads();

        // ---- rescale O accumulators by alpha ----
#pragma unroll
        for (int mi = 0; mi < 2; mi++) {
            float a0 = arow[wm * 32 + mi * 16 + g];
            float a1 = arow[wm * 32 + mi * 16 + g + 8];
#pragma unroll
            for (int ni = 0; ni < 2; ni++) {
                oacc[mi][ni][0] *= a0;
                oacc[mi][ni][1] *= a0;
                oacc[mi][ni][2] *= a1;
                oacc[mi][ni][3] *= a1;
            }
        }

        // ---- O += P @ V (64x64) ----
#pragma unroll
        for (int kk = 0; kk < 64; kk += 8) {
            unsigned af[2][4];
#pragma unroll
            for (int mi = 0; mi < 2; mi++) {
                int m = wm * 32 + mi * 16;
                af[mi][0] = uP[(m + g) * 68 + kk + c];
                af[mi][1] = uP[(m + g + 8) * 68 + kk + c];
                af[mi][2] = uP[(m + g) * 68 + kk + c + 4];
                af[mi][3] = uP[(m + g + 8) * 68 + kk + c + 4];
            }
#pragma unroll
            for (int ni = 0; ni < 2; ni++) {
                int n = wn * 16 + ni * 8 + g;
                unsigned bf[2];
                bf[0] = uV[(kk + c) * 68 + n];
                bf[1] = uV[(kk + c + 4) * 68 + n];
#pragma unroll
                for (int mi = 0; mi < 2; mi++)
                    mma_tf32(oacc[mi][ni], af[mi], bf);
            }
        }
    }

    // ---- epilogue: O / l, write head-interleaved ----
    __syncthreads();
#pragma unroll
    for (int mi = 0; mi < 2; mi++) {
        int rl0 = wm * 32 + mi * 16 + g;
        float i0 = 1.f / lrow[rl0];
        float i1 = 1.f / lrow[rl0 + 8];
        int gr0 = qb * 64 + rl0;
#pragma unroll
        for (int ni = 0; ni < 2; ni++) {
            int col = h * HD + wn * 16 + ni * 8 + 2 * c;
            *reinterpret_cast<float2*>(g_attn + (size_t)gr0 * HID + col) =
                make_float2(oacc[mi][ni][0] * i0, oacc[mi][ni][1] * i0);
            *reinterpret_cast<float2*>(g_attn + (size_t)(gr0 + 8) * HID + col) =
                make_float2(oacc[mi][ni][2] * i1, oacc[mi][ni][3] * i1);
        }
    }
}

// ---------------------------------------------------------------------------
// MoE routing / permutation (fp32 router — expert picks must not flip)
// ---------------------------------------------------------------------------
__global__ void k_reset(void) {
    if (threadIdx.x < NE) {
        g_cnt[threadIdx.x] = 0;
        g_cur[threadIdx.x] = 0;
    }
}

__global__ void k_router(const float* __restrict__ Wr) {
    int t = blockIdx.x;
    int w = threadIdx.x >> 5, lane = threadIdx.x & 31;
    __shared__ float lg[NE];
    const float* xr = g_xn2 + (size_t)t * HID;
    float s = 0.f;
    for (int k = lane; k < HID; k += 32) s += xr[k] * Wr[k * NE + w];
#pragma unroll
    for (int o = 16; o > 0; o >>= 1) s += __shfl_xor_sync(0xffffffffu, s, o);
    if (lane == 0) lg[w] = s;
    __syncthreads();
    if (threadIdx.x == 0) {
        int b0 = 0;
        float v0 = lg[0];
        for (int e = 1; e < NE; e++)
            if (lg[e] > v0) { v0 = lg[e]; b0 = e; }
        int b1 = -1;
        float v1 = -3e38f;
        for (int e = 0; e < NE; e++)
            if (e != b0 && lg[e] > v1) { v1 = lg[e]; b1 = e; }
        float w0 = 1.f / (1.f + __expf(v1 - v0));
        g_eid[2 * t] = b0;
        g_eid[2 * t + 1] = b1;
        g_ew[2 * t] = w0;
        g_ew[2 * t + 1] = 1.f - w0;
        atomicAdd(&g_cnt[b0], 1);
        atomicAdd(&g_cnt[b1], 1);
    }
}

__global__ void k_scan(void) {
    if (threadIdx.x == 0) {
        int a = 0;
        for (int e = 0; e < NE; e++) {
            g_off[e] = a;
            a += g_cnt[e];
        }
        g_off[NE] = a;
    }
}

__global__ void k_scatter(void) {
    int t = blockIdx.x * blockDim.x + threadIdx.x;
    if (t >= SEQ) return;
#pragma unroll
    for (int slot = 0; slot < 2; slot++) {
        int e = g_eid[2 * t + slot];
        int pos = g_off[e] + atomicAdd(&g_cur[e], 1);
        g_ptok[pos] = t;
        g_tslot[2 * t + slot] = pos;
    }
}

__global__ void k_gather(void) {
    int pos = blockIdx.x;
    int tok = g_ptok[pos];
    const float4* src = reinterpret_cast<const float4*>(g_xn2 + (size_t)tok * HID);
    float4* dst = reinterpret_cast<float4*>(g_Xp + (size_t)pos * HID);
    dst[threadIdx.x] = src[threadIdx.x];
}

__global__ void k_silu(void) {
    int idx = blockIdx.x * blockDim.x + threadIdx.x;
    const int total = SLOTS * FF;
    if (idx >= total) return;
    int pos = idx / FF, j = idx - pos * FF;
    float g = g_Hgu[(size_t)pos * (2 * FF) + j];
    float u = g_Hgu[(size_t)pos * (2 * FF) + FF + j];
    float sg = g / (1.f + __expf(-g));
    g_Hact[idx] = sg * u;
}

__global__ void k_combine(float* __restrict__ out) {
    int t = blockIdx.x;
    int i = threadIdx.x;
    int p0 = g_tslot[2 * t], p1 = g_tslot[2 * t + 1];
    float w0 = g_ew[2 * t], w1 = g_ew[2 * t + 1];
    float4 a = reinterpret_cast<const float4*>(g_h1 + (size_t)t * HID)[i];
    float4 b = reinterpret_cast<const float4*>(g_Dn + (size_t)p0 * HID)[i];
    float4 c = reinterpret_cast<const float4*>(g_Dn + (size_t)p1 * HID)[i];
    float4 o = make_float4(a.x + w0 * b.x + w1 * c.x,
                           a.y + w0 * b.y + w1 * c.y,
                           a.z + w0 * b.z + w1 * c.z,
                           a.w + w0 * b.w + w1 * c.w);
    reinterpret_cast<float4*>(out + (size_t)t * HID)[i] = o;
}

// ---------------------------------------------------------------------------
// Launch
// ---------------------------------------------------------------------------
extern "C" void kernel_launch(void* const* d_in, const int* in_sizes, int n_in,
                              void* d_out, int out_size) {
    (void)in_sizes; (void)n_in; (void)out_size;
    const float* x        = (const float*)d_in[0];
    const float* norm1_w  = (const float*)d_in[1];
    const float* w_qkv    = (const float*)d_in[2];
    const float* w_out    = (const float*)d_in[3];
    const float* norm2_w  = (const float*)d_in[4];
    const float* w_router = (const float*)d_in[5];
    const float* w_gateup = (const float*)d_in[6];
    const float* w_down   = (const float*)d_in[7];
    float* out = (float*)d_out;

    cudaFuncSetAttribute(k_attn, cudaFuncAttributeMaxDynamicSharedMemorySize,
                         ATT_SMEM_BYTES);

    k_reset<<<1, 32>>>();
    k_rmsnorm1<<<SEQ, 256>>>(x, norm1_w);
    k_gemm_qkv<<<dim3(SEQ / 128, QKVC / 128), 256>>>(w_qkv);
    k_rope<<<SEQ, 576>>>();
    k_attn<<<dim3(SEQ / 64, NQ), 256, ATT_SMEM_BYTES>>>();
    k_gemm_out<<<dim3(SEQ / 128, HID / 128), 256>>>(w_out, x);
    k_rmsnorm2<<<SEQ, 256>>>(norm2_w);
    k_router<<<SEQ, 512>>>(w_router);
    k_scan<<<1, 32>>>();
    k_scatter<<<(SEQ + 255) / 256, 256>>>();
    k_gather<<<SLOTS, 192>>>();
    k_moe_gemm1<<<dim3(NE * 16, (2 * FF) / 128), 256>>>(w_gateup);
    k_silu<<<(SLOTS * FF + 255) / 256, 256>>>();
    k_moe_gemm2<<<dim3(NE * 16, HID / 128), 256>>>(w_down);
    k_combine<<<SEQ, 192>>>(out);
}

// round 7
// speedup vs baseline: 2.6715x; 1.0464x over previous
#include <cuda_runtime.h>
#include <math.h>

// ---------------------------------------------------------------------------
// Constants
// ---------------------------------------------------------------------------
#define SEQ   2048
#define HID   768
#define NQ    12
#define NKV   3
#define HD    64
#define QKVC  1152          // (NQ + 2*NKV) * HD
#define NE    16
#define FF    1536
#define SLOTS 4096          // SEQ * TOPK

// GEMM smem geometry (3-stage pipeline)
#define SA_STRIDE 20
#define SB_STRIDE 132
#define SA_STAGE  (128 * SA_STRIDE)   // 2560 words
#define SB_STAGE  (16 * SB_STRIDE)    // 2112 words
#define SMEM_SINGLE_B ((3 * SA_STAGE + 3 * SB_STAGE) * 4)       // 56064 B
#define SMEM_DUAL_B   ((3 * SA_STAGE + 6 * SB_STAGE) * 4)       // 81408 B

// ---------------------------------------------------------------------------
// Device scratch (globals only referenced from device code!)
// ---------------------------------------------------------------------------
__device__ float g_xn1[SEQ * HID];
__device__ float g_qkv[SEQ * QKVC];
__device__ float g_Q[NQ * SEQ * HD];
__device__ float g_K[NKV * SEQ * HD];
__device__ float g_V[NKV * SEQ * HD];
__device__ float g_attn[SEQ * HID];
__device__ float g_h1[SEQ * HID];
__device__ float g_xn2[SEQ * HID];
__device__ int   g_eid[SLOTS];
__device__ float g_ew[SLOTS];
__device__ int   g_cnt[NE];
__device__ int   g_off[NE + 1];
__device__ int   g_cur[NE];
__device__ int   g_ptok[SLOTS];
__device__ int   g_tslot[SLOTS];
__device__ float g_Xp[(size_t)SLOTS * HID];
__device__ float g_Hact[(size_t)SLOTS * FF];
__device__ float g_Dn[(size_t)SLOTS * HID];

// ---------------------------------------------------------------------------
// TF32 helpers
// ---------------------------------------------------------------------------
__device__ __forceinline__ unsigned f2tf(float f) {
    unsigned u;
    asm("cvt.rna.tf32.f32 %0, %1;" : "=r"(u) : "f"(f));
    return u;
}

__device__ __forceinline__ void mma_tf32(float d[4], const unsigned a[4],
                                         const unsigned b[2]) {
    asm volatile(
        "mma.sync.aligned.m16n8k8.row.col.f32.tf32.tf32.f32 "
        "{%0,%1,%2,%3}, {%4,%5,%6,%7}, {%8,%9}, {%0,%1,%2,%3};"
        : "+f"(d[0]), "+f"(d[1]), "+f"(d[2]), "+f"(d[3])
        : "r"(a[0]), "r"(a[1]), "r"(a[2]), "r"(a[3]),
          "r"(b[0]), "r"(b[1]));
}

__device__ __forceinline__ void cp16(void* smem_dst, const void* gmem_src, bool pred) {
    unsigned d = (unsigned)__cvta_generic_to_shared(smem_dst);
    int sz = pred ? 16 : 0;
    asm volatile("cp.async.cg.shared.global [%0], [%1], 16, %2;"
                 :: "r"(d), "l"(gmem_src), "r"(sz) : "memory");
}

// ---------------------------------------------------------------------------
// RMSNorm
// ---------------------------------------------------------------------------
__device__ __forceinline__ void rmsnorm_row(const float* __restrict__ xr,
                                            const float* __restrict__ w,
                                            float* __restrict__ yr) {
    float s = 0.f;
    for (int i = threadIdx.x; i < HID; i += 256) {
        float v = xr[i];
        s += v * v;
    }
    __shared__ float red[256];
    red[threadIdx.x] = s;
    __syncthreads();
    for (int o = 128; o > 0; o >>= 1) {
        if (threadIdx.x < o) red[threadIdx.x] += red[threadIdx.x + o];
        __syncthreads();
    }
    float scale = rsqrtf(red[0] / (float)HID + 1e-6f);
    for (int i = threadIdx.x; i < HID; i += 256)
        yr[i] = xr[i] * scale * w[i];
}

__global__ void k_rmsnorm1(const float* __restrict__ x, const float* __restrict__ w) {
    int row = blockIdx.x;
    rmsnorm_row(x + (size_t)row * HID, w, g_xn1 + (size_t)row * HID);
}

__global__ void k_rmsnorm2(const float* __restrict__ w) {
    int row = blockIdx.x;
    rmsnorm_row(g_h1 + (size_t)row * HID, w, g_xn2 + (size_t)row * HID);
}

// ---------------------------------------------------------------------------
// TF32 tensor-core GEMM, 3-stage cp.async pipeline.
// 128x128 tile, 256 threads (8 warps, 2x4), warp tile 64x32, K-step 16.
// ---------------------------------------------------------------------------
__device__ __forceinline__ void gemm_tf32_core3(const float* __restrict__ A, int lda,
                                                const float* __restrict__ B, int ldb,
                                                int K, int rows,
                                                unsigned* SA, unsigned* SB,
                                                float acc[4][4][4]) {
    int tid  = threadIdx.x;
    int warp = tid >> 5, lane = tid & 31;
    int wm = warp >> 2, wn = warp & 3;
    int g  = lane >> 2, c = lane & 3;

    int ar0 = tid >> 2, ar1 = ar0 + 64;
    int akq = (tid & 3) * 4;
    int bkr0 = tid >> 5, bkr1 = bkr0 + 8;
    int bc4 = (tid & 31) * 4;
    bool p0 = ar0 < rows, p1 = ar1 < rows;
    const float* Ar0 = A + (size_t)(p0 ? ar0 : 0) * lda + akq;
    const float* Ar1 = A + (size_t)(p1 ? ar1 : 0) * lda + akq;
    const float* Br0 = B + (size_t)bkr0 * ldb + bc4;
    const float* Br1 = B + (size_t)bkr1 * ldb + bc4;

#define ST1(s, k0)                                                           \
    do {                                                                     \
        unsigned* a_ = SA + (s) * SA_STAGE;                                  \
        unsigned* b_ = SB + (s) * SB_STAGE;                                  \
        cp16(a_ + ar0 * SA_STRIDE + akq, Ar0 + (k0), p0);                    \
        cp16(a_ + ar1 * SA_STRIDE + akq, Ar1 + (k0), p1);                    \
        cp16(b_ + bkr0 * SB_STRIDE + bc4, Br0 + (size_t)(k0) * ldb, true);   \
        cp16(b_ + bkr1 * SB_STRIDE + bc4, Br1 + (size_t)(k0) * ldb, true);   \
        asm volatile("cp.async.commit_group;" ::: "memory");                 \
    } while (0)

    ST1(0, 0);
    ST1(1, 16);
    int buf = 0;
    for (int k0 = 0; k0 < K; k0 += 16) {
        if (k0 + 32 < K) {
            asm volatile("cp.async.wait_group 1;" ::: "memory");
            __syncthreads();
            ST1(buf == 0 ? 2 : buf - 1, k0 + 32);   // (buf+2)%3
        } else {
            asm volatile("cp.async.wait_group 0;" ::: "memory");
            __syncthreads();
        }
        unsigned* a_ = SA + buf * SA_STAGE;
        unsigned* b_ = SB + buf * SB_STAGE;
#pragma unroll
        for (int kk = 0; kk < 16; kk += 8) {
            unsigned af[4][4];
#pragma unroll
            for (int mi = 0; mi < 4; mi++) {
                int m = wm * 64 + mi * 16;
                af[mi][0] = a_[(m + g) * SA_STRIDE + kk + c];
                af[mi][1] = a_[(m + g + 8) * SA_STRIDE + kk + c];
                af[mi][2] = a_[(m + g) * SA_STRIDE + kk + c + 4];
                af[mi][3] = a_[(m + g + 8) * SA_STRIDE + kk + c + 4];
            }
#pragma unroll
            for (int ni = 0; ni < 4; ni++) {
                int n = wn * 32 + ni * 8 + g;
                unsigned bf[2];
                bf[0] = b_[(kk + c) * SB_STRIDE + n];
                bf[1] = b_[(kk + c + 4) * SB_STRIDE + n];
#pragma unroll
                for (int mi = 0; mi < 4; mi++)
                    mma_tf32(acc[mi][ni], af[mi], bf);
            }
        }
        buf = (buf == 2) ? 0 : buf + 1;
    }
#undef ST1
}

// QKV projection: g_qkv = g_xn1 @ w_qkv   (2048 x 768 x 1152)
__global__ void __launch_bounds__(256) k_gemm_qkv(const float* __restrict__ W) {
    extern __shared__ unsigned dsm[];
    int mb = blockIdx.x, nb = blockIdx.y;
    float acc[4][4][4] = {};
    gemm_tf32_core3(g_xn1 + (size_t)mb * 128 * HID, HID, W + nb * 128, QKVC,
                    HID, 128, dsm, dsm + 3 * SA_STAGE, acc);
    int warp = threadIdx.x >> 5, lane = threadIdx.x & 31;
    int wm = warp >> 2, wn = warp & 3, g = lane >> 2, c = lane & 3;
#pragma unroll
    for (int mi = 0; mi < 4; mi++) {
#pragma unroll
        for (int ni = 0; ni < 4; ni++) {
            int r = mb * 128 + wm * 64 + mi * 16 + g;
            int col = nb * 128 + wn * 32 + ni * 8 + 2 * c;
            *reinterpret_cast<float2*>(g_qkv + (size_t)r * QKVC + col) =
                make_float2(acc[mi][ni][0], acc[mi][ni][1]);
            *reinterpret_cast<float2*>(g_qkv + (size_t)(r + 8) * QKVC + col) =
                make_float2(acc[mi][ni][2], acc[mi][ni][3]);
        }
    }
}

// Out projection + residual: g_h1 = x + g_attn @ w_out   (2048 x 768 x 768)
__global__ void __launch_bounds__(256) k_gemm_out(const float* __restrict__ W,
                                                  const float* __restrict__ xres) {
    extern __shared__ unsigned dsm[];
    int mb = blockIdx.x, nb = blockIdx.y;
    float acc[4][4][4] = {};
    gemm_tf32_core3(g_attn + (size_t)mb * 128 * HID, HID, W + nb * 128, HID,
                    HID, 128, dsm, dsm + 3 * SA_STAGE, acc);
    int warp = threadIdx.x >> 5, lane = threadIdx.x & 31;
    int wm = warp >> 2, wn = warp & 3, g = lane >> 2, c = lane & 3;
#pragma unroll
    for (int mi = 0; mi < 4; mi++) {
#pragma unroll
        for (int ni = 0; ni < 4; ni++) {
            int r = mb * 128 + wm * 64 + mi * 16 + g;
            int col = nb * 128 + wn * 32 + ni * 8 + 2 * c;
            size_t o0 = (size_t)r * HID + col;
            size_t o1 = (size_t)(r + 8) * HID + col;
            float2 x0 = *reinterpret_cast<const float2*>(xres + o0);
            float2 x1 = *reinterpret_cast<const float2*>(xres + o1);
            *reinterpret_cast<float2*>(g_h1 + o0) =
                make_float2(x0.x + acc[mi][ni][0], x0.y + acc[mi][ni][1]);
            *reinterpret_cast<float2*>(g_h1 + o1) =
                make_float2(x1.x + acc[mi][ni][2], x1.y + acc[mi][ni][3]);
        }
    }
}

// MoE GEMM1 fused with SiLU*up: Hact[slot] = silu(Xp@Wg) * (Xp@Wu)
// Dual accumulator: gate cols nb*128, up cols nb*128+FF share the A tile.
__global__ void __launch_bounds__(256) k_moe_gemm1(const float* __restrict__ Wgu) {
    extern __shared__ unsigned dsm[];
    int e = blockIdx.x >> 4, mb = blockIdx.x & 15, nb = blockIdx.y;
    int r0 = g_off[e];
    int rows_e = g_off[e + 1] - r0;
    int rbase = mb * 128;
    if (rbase >= rows_e) return;
    int rows = min(128, rows_e - rbase);

    unsigned* SA  = dsm;
    unsigned* SBg = dsm + 3 * SA_STAGE;
    unsigned* SBu = SBg + 3 * SB_STAGE;

    const float* A  = g_Xp + (size_t)(r0 + rbase) * HID;
    const float* Bg = Wgu + (size_t)e * HID * (2 * FF) + nb * 128;
    const float* Bu = Bg + FF;

    int tid  = threadIdx.x;
    int warp = tid >> 5, lane = tid & 31;
    int wm = warp >> 2, wn = warp & 3;
    int g  = lane >> 2, c = lane & 3;
    int ar0 = tid >> 2, ar1 = ar0 + 64;
    int akq = (tid & 3) * 4;
    int bkr0 = tid >> 5, bkr1 = bkr0 + 8;
    int bc4 = (tid & 31) * 4;
    bool p0 = ar0 < rows, p1 = ar1 < rows;
    const float* Ar0 = A + (size_t)(p0 ? ar0 : 0) * HID + akq;
    const float* Ar1 = A + (size_t)(p1 ? ar1 : 0) * HID + akq;
    const float* Bg0 = Bg + (size_t)bkr0 * (2 * FF) + bc4;
    const float* Bg1 = Bg + (size_t)bkr1 * (2 * FF) + bc4;
    const float* Bu0 = Bu + (size_t)bkr0 * (2 * FF) + bc4;
    const float* Bu1 = Bu + (size_t)bkr1 * (2 * FF) + bc4;

    float accg[4][4][4] = {};
    float accu[4][4][4] = {};

#define ST2(s, k0)                                                                 \
    do {                                                                           \
        unsigned* a_  = SA + (s) * SA_STAGE;                                       \
        unsigned* bg_ = SBg + (s) * SB_STAGE;                                      \
        unsigned* bu_ = SBu + (s) * SB_STAGE;                                      \
        cp16(a_ + ar0 * SA_STRIDE + akq, Ar0 + (k0), p0);                          \
        cp16(a_ + ar1 * SA_STRIDE + akq, Ar1 + (k0), p1);                          \
        cp16(bg_ + bkr0 * SB_STRIDE + bc4, Bg0 + (size_t)(k0) * (2 * FF), true);   \
        cp16(bg_ + bkr1 * SB_STRIDE + bc4, Bg1 + (size_t)(k0) * (2 * FF), true);   \
        cp16(bu_ + bkr0 * SB_STRIDE + bc4, Bu0 + (size_t)(k0) * (2 * FF), true);   \
        cp16(bu_ + bkr1 * SB_STRIDE + bc4, Bu1 + (size_t)(k0) * (2 * FF), true);   \
        asm volatile("cp.async.commit_group;" ::: "memory");                       \
    } while (0)

    ST2(0, 0);
    ST2(1, 16);
    int buf = 0;
    for (int k0 = 0; k0 < HID; k0 += 16) {
        if (k0 + 32 < HID) {
            asm volatile("cp.async.wait_group 1;" ::: "memory");
            __syncthreads();
            ST2(buf == 0 ? 2 : buf - 1, k0 + 32);
        } else {
            asm volatile("cp.async.wait_group 0;" ::: "memory");
            __syncthreads();
        }
        unsigned* a_  = SA + buf * SA_STAGE;
        unsigned* bg_ = SBg + buf * SB_STAGE;
        unsigned* bu_ = SBu + buf * SB_STAGE;
#pragma unroll
        for (int kk = 0; kk < 16; kk += 8) {
            unsigned af[4][4];
#pragma unroll
            for (int mi = 0; mi < 4; mi++) {
                int m = wm * 64 + mi * 16;
                af[mi][0] = a_[(m + g) * SA_STRIDE + kk + c];
                af[mi][1] = a_[(m + g + 8) * SA_STRIDE + kk + c];
                af[mi][2] = a_[(m + g) * SA_STRIDE + kk + c + 4];
                af[mi][3] = a_[(m + g + 8) * SA_STRIDE + kk + c + 4];
            }
#pragma unroll
            for (int ni = 0; ni < 4; ni++) {
                int n = wn * 32 + ni * 8 + g;
                unsigned bfg[2], bfu[2];
                bfg[0] = bg_[(kk + c) * SB_STRIDE + n];
                bfg[1] = bg_[(kk + c + 4) * SB_STRIDE + n];
                bfu[0] = bu_[(kk + c) * SB_STRIDE + n];
                bfu[1] = bu_[(kk + c + 4) * SB_STRIDE + n];
#pragma unroll
                for (int mi = 0; mi < 4; mi++) {
                    mma_tf32(accg[mi][ni], af[mi], bfg);
                    mma_tf32(accu[mi][ni], af[mi], bfu);
                }
            }
        }
        buf = (buf == 2) ? 0 : buf + 1;
    }
#undef ST2

    // Fused SiLU(gate) * up epilogue -> g_Hact
    float* Cp = g_Hact + (size_t)(r0 + rbase) * FF + nb * 128;
#pragma unroll
    for (int mi = 0; mi < 4; mi++) {
#pragma unroll
        for (int ni = 0; ni < 4; ni++) {
            int rr = wm * 64 + mi * 16 + g;
            int col = wn * 32 + ni * 8 + 2 * c;
            float h[4];
#pragma unroll
            for (int j = 0; j < 4; j++) {
                float gv = accg[mi][ni][j];
                h[j] = gv / (1.f + __expf(-gv)) * accu[mi][ni][j];
            }
            if (rr < rows)
                *reinterpret_cast<float2*>(Cp + (size_t)rr * FF + col) =
                    make_float2(h[0], h[1]);
            if (rr + 8 < rows)
                *reinterpret_cast<float2*>(Cp + (size_t)(rr + 8) * FF + col) =
                    make_float2(h[2], h[3]);
        }
    }
}

// MoE GEMM2: Dn[slot] = Hact[slot] @ w_down[e]   (rows_e x 1536 x 768)
__global__ void __launch_bounds__(256) k_moe_gemm2(const float* __restrict__ Wd) {
    extern __shared__ unsigned dsm[];
    int e = blockIdx.x >> 4, mb = blockIdx.x & 15, nb = blockIdx.y;
    int r0 = g_off[e];
    int rows_e = g_off[e + 1] - r0;
    int rbase = mb * 128;
    if (rbase >= rows_e) return;
    int rows = min(128, rows_e - rbase);
    float acc[4][4][4] = {};
    gemm_tf32_core3(g_Hact + (size_t)(r0 + rbase) * FF, FF,
                    Wd + (size_t)e * FF * HID + nb * 128, HID, FF, rows,
                    dsm, dsm + 3 * SA_STAGE, acc);
    int warp = threadIdx.x >> 5, lane = threadIdx.x & 31;
    int wm = warp >> 2, wn = warp & 3, g = lane >> 2, c = lane & 3;
    float* Cp = g_Dn + (size_t)(r0 + rbase) * HID + nb * 128;
#pragma unroll
    for (int mi = 0; mi < 4; mi++) {
#pragma unroll
        for (int ni = 0; ni < 4; ni++) {
            int rr = wm * 64 + mi * 16 + g;
            int col = wn * 32 + ni * 8 + 2 * c;
            if (rr < rows)
                *reinterpret_cast<float2*>(Cp + (size_t)rr * HID + col) =
                    make_float2(acc[mi][ni][0], acc[mi][ni][1]);
            if (rr + 8 < rows)
                *reinterpret_cast<float2*>(Cp + (size_t)(rr + 8) * HID + col) =
                    make_float2(acc[mi][ni][2], acc[mi][ni][3]);
        }
    }
}

// ---------------------------------------------------------------------------
// RoPE + split into head-major Q/K/V
// ---------------------------------------------------------------------------
__global__ void k_rope(void) {
    int s = blockIdx.x;
    int p = threadIdx.x;
    const float* row = g_qkv + (size_t)s * QKVC;
    if (p < 384) {
        int h = p >> 5, i = p & 31;
        float v0 = row[h * HD + 2 * i];
        float v1 = row[h * HD + 2 * i + 1];
        float inv = powf(10000.f, -(float)(2 * i) / (float)HD);
        float ang = (float)s * inv;
        float sn, cs;
        sincosf(ang, &sn, &cs);
        float* dst = g_Q + ((size_t)h * SEQ + s) * HD;
        dst[2 * i]     = v0 * cs - v1 * sn;
        dst[2 * i + 1] = v0 * sn + v1 * cs;
    } else if (p < 480) {
        int q = p - 384;
        int h = q >> 5, i = q & 31;
        float v0 = row[NQ * HD + h * HD + 2 * i];
        float v1 = row[NQ * HD + h * HD + 2 * i + 1];
        float inv = powf(10000.f, -(float)(2 * i) / (float)HD);
        float ang = (float)s * inv;
        float sn, cs;
        sincosf(ang, &sn, &cs);
        float* dst = g_K + ((size_t)h * SEQ + s) * HD;
        dst[2 * i]     = v0 * cs - v1 * sn;
        dst[2 * i + 1] = v0 * sn + v1 * cs;
    } else {
        int q = p - 480;
        int h = q >> 5, i = q & 31;
        float* dst = g_V + ((size_t)h * SEQ + s) * HD;
        dst[2 * i]     = row[(NQ + NKV) * HD + h * HD + 2 * i];
        dst[2 * i + 1] = row[(NQ + NKV) * HD + h * HD + 2 * i + 1];
    }
}

// ---------------------------------------------------------------------------
// Flash attention, TF32 tensor cores. Block = (64-query tile, head).
// ---------------------------------------------------------------------------
#define ATT_SMEM_BYTES ((4 * 64 * 68 + 64 * 65 + 3 * 64) * 4)

__global__ void k_attn(void) {
    extern __shared__ unsigned smu[];
    unsigned* uQ = smu;               // [64][68] tf32
    unsigned* uK = uQ + 64 * 68;      // [64][68] tf32
    unsigned* uV = uK + 64 * 68;      // [64][68] tf32
    unsigned* uP = uV + 64 * 68;      // [64][68] tf32
    float* Sm    = (float*)(uP + 64 * 68);  // [64][65]
    float* mrow  = Sm + 64 * 65;
    float* lrow  = mrow + 64;
    float* arow  = lrow + 64;

    int qb = gridDim.x - 1 - blockIdx.x;   // heavy tiles first (load balance)
    int h  = blockIdx.y;
    int kvh = h >> 2;                      // REP = 4
    int tid = threadIdx.x;
    int warp = tid >> 5, lane = tid & 31;
    int wm = warp >> 2, wn = warp & 3;     // 2 x 4 warp grid
    int g  = lane >> 2, c = lane & 3;

    const float* Qb = g_Q + ((size_t)h * SEQ + qb * 64) * HD;
    for (int e = tid; e < 4096; e += 256) {
        int r = e >> 6, d = e & 63;
        uQ[r * 68 + d] = f2tf(Qb[r * HD + d] * 0.125f);  // 1/sqrt(64)
    }
    if (tid < 64) { mrow[tid] = -1e30f; lrow[tid] = 0.f; }

    float oacc[2][2][4] = {};
    for (int kb = 0; kb <= qb; kb++) {
        const float* Kb = g_K + ((size_t)kvh * SEQ + kb * 64) * HD;
        const float* Vb = g_V + ((size_t)kvh * SEQ + kb * 64) * HD;
        __syncthreads();                   // uK/uV free (prev PV done)
        for (int e = tid; e < 4096; e += 256) {
            int r = e >> 6, d = e & 63;
            uK[r * 68 + d] = f2tf(Kb[r * HD + d]);
            uV[r * 68 + d] = f2tf(Vb[r * HD + d]);
        }
        __syncthreads();

        // ---- S = Q @ K^T (64x64), warp tile 32x16 ----
        float sacc[2][2][4] = {};
#pragma unroll
        for (int kk = 0; kk < 64; kk += 8) {
            unsigned af[2][4];
#pragma unroll
            for (int mi = 0; mi < 2; mi++) {
                int m = wm * 32 + mi * 16;
                af[mi][0] = uQ[(m + g) * 68 + kk + c];
                af[mi][1] = uQ[(m + g + 8) * 68 + kk + c];
                af[mi][2] = uQ[(m + g) * 68 + kk + c + 4];
                af[mi][3] = uQ[(m + g + 8) * 68 + kk + c + 4];
            }
#pragma unroll
            for (int ni = 0; ni < 2; ni++) {
                int n = wn * 16 + ni * 8 + g;
                unsigned bf[2];
                bf[0] = uK[n * 68 + kk + c];
                bf[1] = uK[n * 68 + kk + c + 4];
#pragma unroll
                for (int mi = 0; mi < 2; mi++)
                    mma_tf32(sacc[mi][ni], af[mi], bf);
            }
        }
        // write masked S to smem
        bool diag = (kb == qb);
#pragma unroll
        for (int mi = 0; mi < 2; mi++) {
#pragma unroll
            for (int ni = 0; ni < 2; ni++) {
                int r0 = wm * 32 + mi * 16 + g;
                int cl = wn * 16 + ni * 8 + 2 * c;
                float v0 = sacc[mi][ni][0], v1 = sacc[mi][ni][1];
                float v2 = sacc[mi][ni][2], v3 = sacc[mi][ni][3];
                if (diag) {
                    if (cl > r0)     v0 = -1e30f;
                    if (cl + 1 > r0) v1 = -1e30f;
                    if (cl > r0 + 8)     v2 = -1e30f;
                    if (cl + 1 > r0 + 8) v3 = -1e30f;
                }
                Sm[r0 * 65 + cl]           = v0;
                Sm[r0 * 65 + cl + 1]       = v1;
                Sm[(r0 + 8) * 65 + cl]     = v2;
                Sm[(r0 + 8) * 65 + cl + 1] = v3;
            }
        }
        __syncthreads();

        // ---- online softmax: 4 lanes per row, write P (tf32) row-major ----
        {
            int i  = tid >> 2;
            int jq = (tid & 3) * 16;
            float mx = -1e30f;
#pragma unroll
            for (int j = 0; j < 16; j++) mx = fmaxf(mx, Sm[i * 65 + jq + j]);
            mx = fmaxf(mx, __shfl_xor_sync(0xffffffffu, mx, 1));
            mx = fmaxf(mx, __shfl_xor_sync(0xffffffffu, mx, 2));
            float mold = mrow[i];
            mx = fmaxf(mx, mold);
            float sum = 0.f;
#pragma unroll
            for (int j = 0; j < 16; j++) {
                float p = __expf(Sm[i * 65 + jq + j] - mx);
                uP[i * 68 + jq + j] = f2tf(p);
                sum += p;
            }
            sum += __shfl_xor_sync(0xffffffffu, sum, 1);
            sum += __shfl_xor_sync(0xffffffffu, sum, 2);
            if ((tid & 3) == 0) {
                float al = __expf(mold - mx);
                lrow[i] = lrow[i] * al + sum;
                mrow[i] = mx;
                arow[i] = al;
            }
        }
        __syncthreads();

        // ---- rescale O accumulators by alpha ----
#pragma unroll
        for (int mi = 0; mi < 2; mi++) {
            float a0 = arow[wm * 32 + mi * 16 + g];
            float a1 = arow[wm * 32 + mi * 16 + g + 8];
#pragma unroll
            for (int ni = 0; ni < 2; ni++) {
                oacc[mi][ni][0] *= a0;
                oacc[mi][ni][1] *= a0;
                oacc[mi][ni][2] *= a1;
                oacc[mi][ni][3] *= a1;
            }
        }

        // ---- O += P @ V (64x64) ----
#pragma unroll
        for (int kk = 0; kk < 64; kk += 8) {
            unsigned af[2][4];
#pragma unroll
            for (int mi = 0; mi < 2; mi++) {
                int m = wm * 32 + mi * 16;
                af[mi][0] = uP[(m + g) * 68 + kk + c];
                af[mi][1] = uP[(m + g + 8) * 68 + kk + c];
                af[mi][2] = uP[(m + g) * 68 + kk + c + 4];
                af[mi][3] = uP[(m + g + 8) * 68 + kk + c + 4];
            }
#pragma unroll
            for (int ni = 0; ni < 2; ni++) {
                int n = wn * 16 + ni * 8 + g;
                unsigned bf[2];
                bf[0] = uV[(kk + c) * 68 + n];
                bf[1] = uV[(kk + c + 4) * 68 + n];
#pragma unroll
                for (int mi = 0; mi < 2; mi++)
                    mma_tf32(oacc[mi][ni], af[mi], bf);
            }
        }
    }

    // ---- epilogue: O / l, write head-interleaved ----
    __syncthreads();
#pragma unroll
    for (int mi = 0; mi < 2; mi++) {
        int rl0 = wm * 32 + mi * 16 + g;
        float i0 = 1.f / lrow[rl0];
        float i1 = 1.f / lrow[rl0 + 8];
        int gr0 = qb * 64 + rl0;
#pragma unroll
        for (int ni = 0; ni < 2; ni++) {
            int col = h * HD + wn * 16 + ni * 8 + 2 * c;
            *reinterpret_cast<float2*>(g_attn + (size_t)gr0 * HID + col) =
                make_float2(oacc[mi][ni][0] * i0, oacc[mi][ni][1] * i0);
            *reinterpret_cast<float2*>(g_attn + (size_t)(gr0 + 8) * HID + col) =
                make_float2(oacc[mi][ni][2] * i1, oacc[mi][ni][3] * i1);
        }
    }
}

// ---------------------------------------------------------------------------
// MoE routing / permutation (fp32 router — expert picks must not flip)
// ---------------------------------------------------------------------------
__global__ void k_reset(void) {
    if (threadIdx.x < NE) {
        g_cnt[threadIdx.x] = 0;
        g_cur[threadIdx.x] = 0;
    }
}

__global__ void k_router(const float* __restrict__ Wr) {
    int t = blockIdx.x;
    int w = threadIdx.x >> 5, lane = threadIdx.x & 31;
    __shared__ float lg[NE];
    const float* xr = g_xn2 + (size_t)t * HID;
    float s = 0.f;
    for (int k = lane; k < HID; k += 32) s += xr[k] * Wr[k * NE + w];
#pragma unroll
    for (int o = 16; o > 0; o >>= 1) s += __shfl_xor_sync(0xffffffffu, s, o);
    if (lane == 0) lg[w] = s;
    __syncthreads();
    if (threadIdx.x == 0) {
        int b0 = 0;
        float v0 = lg[0];
        for (int e = 1; e < NE; e++)
            if (lg[e] > v0) { v0 = lg[e]; b0 = e; }
        int b1 = -1;
        float v1 = -3e38f;
        for (int e = 0; e < NE; e++)
            if (e != b0 && lg[e] > v1) { v1 = lg[e]; b1 = e; }
        float w0 = 1.f / (1.f + __expf(v1 - v0));
        g_eid[2 * t] = b0;
        g_eid[2 * t + 1] = b1;
        g_ew[2 * t] = w0;
        g_ew[2 * t + 1] = 1.f - w0;
        atomicAdd(&g_cnt[b0], 1);
        atomicAdd(&g_cnt[b1], 1);
    }
}

__global__ void k_scan(void) {
    if (threadIdx.x == 0) {
        int a = 0;
        for (int e = 0; e < NE; e++) {
            g_off[e] = a;
            a += g_cnt[e];
        }
        g_off[NE] = a;
    }
}

__global__ void k_scatter(void) {
    int t = blockIdx.x * blockDim.x + threadIdx.x;
    if (t >= SEQ) return;
#pragma unroll
    for (int slot = 0; slot < 2; slot++) {
        int e = g_eid[2 * t + slot];
        int pos = g_off[e] + atomicAdd(&g_cur[e], 1);
        g_ptok[pos] = t;
        g_tslot[2 * t + slot] = pos;
    }
}

__global__ void k_gather(void) {
    int pos = blockIdx.x;
    int tok = g_ptok[pos];
    const float4* src = reinterpret_cast<const float4*>(g_xn2 + (size_t)tok * HID);
    float4* dst = reinterpret_cast<float4*>(g_Xp + (size_t)pos * HID);
    dst[threadIdx.x] = src[threadIdx.x];
}

__global__ void k_combine(float* __restrict__ out) {
    int t = blockIdx.x;
    int i = threadIdx.x;
    int p0 = g_tslot[2 * t], p1 = g_tslot[2 * t + 1];
    float w0 = g_ew[2 * t], w1 = g_ew[2 * t + 1];
    float4 a = reinterpret_cast<const float4*>(g_h1 + (size_t)t * HID)[i];
    float4 b = reinterpret_cast<const float4*>(g_Dn + (size_t)p0 * HID)[i];
    float4 c = reinterpret_cast<const float4*>(g_Dn + (size_t)p1 * HID)[i];
    float4 o = make_float4(a.x + w0 * b.x + w1 * c.x,
                           a.y + w0 * b.y + w1 * c.y,
                           a.z + w0 * b.z + w1 * c.z,
                           a.w + w0 * b.w + w1 * c.w);
    reinterpret_cast<float4*>(out + (size_t)t * HID)[i] = o;
}

// ---------------------------------------------------------------------------
// Launch
// ---------------------------------------------------------------------------
extern "C" void kernel_launch(void* const* d_in, const int* in_sizes, int n_in,
                              void* d_out, int out_size) {
    (void)in_sizes; (void)n_in; (void)out_size;
    const float* x        = (const float*)d_in[0];
    const float* norm1_w  = (const float*)d_in[1];
    const float* w_qkv    = (const float*)d_in[2];
    const float* w_out    = (const float*)d_in[3];
    const float* norm2_w  = (const float*)d_in[4];
    const float* w_router = (const float*)d_in[5];
    const float* w_gateup = (const float*)d_in[6];
    const float* w_down   = (const float*)d_in[7];
    float* out = (float*)d_out;

    cudaFuncSetAttribute(k_attn, cudaFuncAttributeMaxDynamicSharedMemorySize,
                         ATT_SMEM_BYTES);
    cudaFuncSetAttribute(k_gemm_qkv, cudaFuncAttributeMaxDynamicSharedMemorySize,
                         SMEM_SINGLE_B);
    cudaFuncSetAttribute(k_gemm_out, cudaFuncAttributeMaxDynamicSharedMemorySize,
                         SMEM_SINGLE_B);
    cudaFuncSetAttribute(k_moe_gemm1, cudaFuncAttributeMaxDynamicSharedMemorySize,
                         SMEM_DUAL_B);
    cudaFuncSetAttribute(k_moe_gemm2, cudaFuncAttributeMaxDynamicSharedMemorySize,
                         SMEM_SINGLE_B);

    k_reset<<<1, 32>>>();
    k_rmsnorm1<<<SEQ, 256>>>(x, norm1_w);
    k_gemm_qkv<<<dim3(SEQ / 128, QKVC / 128), 256, SMEM_SINGLE_B>>>(w_qkv);
    k_rope<<<SEQ, 576>>>();
    k_attn<<<dim3(SEQ / 64, NQ), 256, ATT_SMEM_BYTES>>>();
    k_gemm_out<<<dim3(SEQ / 128, HID / 128), 256, SMEM_SINGLE_B>>>(w_out, x);
    k_rmsnorm2<<<SEQ, 256>>>(norm2_w);
    k_router<<<SEQ, 512>>>(w_router);
    k_scan<<<1, 32>>>();
    k_scatter<<<(SEQ + 255) / 256, 256>>>();
    k_gather<<<SLOTS, 192>>>();
    k_moe_gemm1<<<dim3(NE * 16, FF / 128), 256, SMEM_DUAL_B>>>(w_gateup);
    k_moe_gemm2<<<dim3(NE * 16, HID / 128), 256, SMEM_SINGLE_B>>>(w_down);
    k_combine<<<SEQ, 192>>>(out);
}